// round 4
// baseline (speedup 1.0000x reference)
#include <cuda_runtime.h>
#include <cstdint>
#include <math.h>

#define Bz 32
#define Sz 64
#define Tz 48
#define Ez 128
#define Hz 256
#define HDz 512
#define Vz 32001
#define GEz 1024   /* 4H  */
#define GDz 2048   /* 4HD */
#define KEz 384    /* E+H  */
#define KDz 640    /* E+HD */

// ---------------- device scratch (static, allocation-free) ----------------
__device__ float g_x[Bz*Sz*Ez];
__device__ float g_di[Bz*Tz*Ez];
__device__ float g_WTf[KEz*GEz];
__device__ float g_WTb[KEz*GEz];
__device__ float g_WTd[KDz*GDz];
__device__ float g_W2T[HDz*HDz];
__device__ float g_enc[Bz*Sz*2*Hz];
__device__ float g_kp[Bz*Sz*HDz];
__device__ float g_hf[Bz*Hz], g_cf[Bz*Hz], g_hb[Bz*Hz], g_cb[Bz*Hz];
__device__ float g_hd[Bz*HDz], g_cd[Bz*HDz];
__device__ float g_gf[Bz*GEz], g_gb[Bz*GEz], g_gd[Bz*GDz];
__device__ float g_qp[Bz*HDz];
__device__ float g_hctx[Bz*Tz*HDz];
__device__ float g_rnll[Bz*Tz], g_rmsk[Bz*Tz];

__device__ __forceinline__ float sigf(float x){ return 1.f/(1.f+expf(-x)); }

// ---------------- prep: embeddings, K-major weight concat+transpose, zero states ----
__global__ void k_prep(const int* __restrict__ iseq, const int* __restrict__ oseq,
                       const float* __restrict__ es, const float* __restrict__ et,
                       const float* __restrict__ Wihf, const float* __restrict__ Whhf,
                       const float* __restrict__ Wihb, const float* __restrict__ Whhb,
                       const float* __restrict__ Wihd, const float* __restrict__ Whhd,
                       const float* __restrict__ W2) {
  const int N1 = Bz*Sz*Ez;            // 262144
  const int N2 = Bz*Tz*Ez;            // 196608
  const int N3 = KEz*GEz;             // 393216
  const int N5 = KDz*GDz;             // 1310720
  const int N6 = HDz*HDz;             // 262144
  const int NZ = 4*Bz*Hz + 2*Bz*HDz;  // 65536
  const int total = N1 + N2 + 2*N3 + N5 + N6 + NZ;
  for (int idx = blockIdx.x*blockDim.x + threadIdx.x; idx < total; idx += gridDim.x*blockDim.x) {
    int i = idx;
    if (i < N1) { int e = i % Ez; int bs = i / Ez;
      g_x[i] = es[(size_t)iseq[bs]*Ez + e]; continue; }
    i -= N1;
    if (i < N2) { int e = i % Ez; int bt = i / Ez; int t = bt % Tz; int b = bt / Tz;
      g_di[i] = (t==0) ? 0.f : et[(size_t)oseq[b*Tz + t-1]*Ez + e]; continue; }
    i -= N2;
    if (i < N3) { int g = i % GEz; int k = i / GEz;
      g_WTf[i] = (k < Ez) ? Wihf[g*Ez + k] : Whhf[g*Hz + (k-Ez)]; continue; }
    i -= N3;
    if (i < N3) { int g = i % GEz; int k = i / GEz;
      g_WTb[i] = (k < Ez) ? Wihb[g*Ez + k] : Whhb[g*Hz + (k-Ez)]; continue; }
    i -= N3;
    if (i < N5) { int g = i % GDz; int k = i / GDz;
      g_WTd[i] = (k < Ez) ? Wihd[g*Ez + k] : Whhd[(size_t)g*HDz + (k-Ez)]; continue; }
    i -= N5;
    if (i < N6) { int n = i % HDz; int k = i / HDz;
      g_W2T[i] = W2[n*HDz + k]; continue; }
    i -= N6;
    if (i < 8192)       g_hf[i] = 0.f;
    else if (i < 16384) g_cf[i-8192] = 0.f;
    else if (i < 24576) g_hb[i-16384] = 0.f;
    else if (i < 32768) g_cb[i-24576] = 0.f;
    else if (i < 49152) g_hd[i-32768] = 0.f;
    else                g_cd[i-49152] = 0.f;
  }
}

// ---------------- encoder gates, both directions in one launch ----------------
// grid 128 = btile(2) x gtile(32) x dir(2); 256 thr; each thread: 2 gates x 1 batch
__global__ void __launch_bounds__(256) k_enc_gates(int t, const float* __restrict__ bf,
                                                   const float* __restrict__ bb) {
  int bt  = blockIdx.x & 1;
  int gt  = (blockIdx.x >> 1) & 31;
  int dir = blockIdx.x >> 6;
  int time = dir ? (Sz-1-t) : t;
  const float* WT   = dir ? g_WTb : g_WTf;
  const float* hbuf = dir ? g_hb  : g_hf;
  const float* bias = dir ? bb    : bf;
  float*       gout = dir ? g_gb  : g_gf;

  __shared__ float sh[16][KEz];  // 24KB: [b][k] = [x ; h]
  int wid = threadIdx.x >> 5, lane = threadIdx.x & 31;
  for (int bi = wid; bi < 16; bi += 8) {
    int b = bt*16 + bi;
    const float* xp = g_x + ((size_t)(b*Sz + time))*Ez;
    for (int k = lane; k < Ez; k += 32) sh[bi][k] = xp[k];
    const float* hp = hbuf + b*Hz;
    for (int k = lane; k < Hz; k += 32) sh[bi][Ez + k] = hp[k];
  }
  __syncthreads();

  int gq = threadIdx.x & 15, bi = threadIdx.x >> 4;
  int g0 = gt*32 + gq*2;
  const float* wp = WT + g0;
  const float* xr = sh[bi];
  float a0 = 0.f, a1 = 0.f;
#pragma unroll 8
  for (int k = 0; k < KEz; k++) {
    float2 w = *(const float2*)(wp + (size_t)k*GEz);
    float x = xr[k];
    a0 = fmaf(w.x, x, a0); a1 = fmaf(w.y, x, a1);
  }
  int b = bt*16 + bi;
  gout[b*GEz + g0]     = a0 + bias[g0];
  gout[b*GEz + g0 + 1] = a1 + bias[g0 + 1];
}

// ---------------- encoder cell + masked enc output; grid 64 x 256 ----------------
__global__ void __launch_bounds__(256) k_enc_cell(int t, const int* __restrict__ lens) {
  int idx = blockIdx.x*256 + threadIdx.x;
  int dir = idx >= Bz*Hz;
  int r = dir ? idx - Bz*Hz : idx;
  int b = r >> 8, j = r & 255;
  int time = dir ? (Sz-1-t) : t;
  bool valid = time < lens[b];
  const float* gbuf = dir ? g_gb : g_gf;
  float gi = gbuf[b*GEz + j];
  float gf = gbuf[b*GEz + Hz + j];
  float gc = gbuf[b*GEz + 2*Hz + j];
  float go = gbuf[b*GEz + 3*Hz + j];
  float* cbuf = dir ? g_cb : g_cf;
  float* hbuf = dir ? g_hb : g_hf;
  float c = cbuf[r];
  float cn = sigf(gf)*c + sigf(gi)*tanhf(gc);
  float hn = sigf(go)*tanhf(cn);
  if (!dir || valid) { cbuf[r] = cn; hbuf[r] = hn; }   // fwd: always; bwd: only valid
  g_enc[((size_t)(b*Sz + time))*(2*Hz) + dir*Hz + j] = valid ? hn : 0.f;
}

// ---------------- decoder gates; grid 128 = btile(2) x gtile(64); 256 thr ----------
__global__ void __launch_bounds__(256) k_dec_gates(int t, const float* __restrict__ bd) {
  int bt = blockIdx.x & 1;
  int gt = blockIdx.x >> 1;
  __shared__ float sh[16][KDz];  // 40KB
  int wid = threadIdx.x >> 5, lane = threadIdx.x & 31;
  for (int bi = wid; bi < 16; bi += 8) {
    int b = bt*16 + bi;
    const float* xp = g_di + ((size_t)(b*Tz + t))*Ez;
    for (int k = lane; k < Ez; k += 32) sh[bi][k] = xp[k];
    const float* hp = g_hd + b*HDz;
    for (int k = lane; k < HDz; k += 32) sh[bi][Ez + k] = hp[k];
  }
  __syncthreads();
  int gq = threadIdx.x & 15, bi = threadIdx.x >> 4;
  int g0 = gt*32 + gq*2;
  const float* wp = g_WTd + g0;
  const float* xr = sh[bi];
  float a0 = 0.f, a1 = 0.f;
#pragma unroll 8
  for (int k = 0; k < KDz; k++) {
    float2 w = *(const float2*)(wp + (size_t)k*GDz);
    float x = xr[k];
    a0 = fmaf(w.x, x, a0); a1 = fmaf(w.y, x, a1);
  }
  int b = bt*16 + bi;
  g_gd[b*GDz + g0]     = a0 + bd[g0];
  g_gd[b*GDz + g0 + 1] = a1 + bd[g0 + 1];
}

// ---------------- decoder cell; grid 64 x 256 over B*HD ----------------
__global__ void __launch_bounds__(256) k_dec_cell() {
  int idx = blockIdx.x*256 + threadIdx.x;
  int b = idx >> 9, j = idx & 511;
  float gi = g_gd[b*GDz + j];
  float gf = g_gd[b*GDz + HDz + j];
  float gc = g_gd[b*GDz + 2*HDz + j];
  float go = g_gd[b*GDz + 3*HDz + j];
  float c = g_cd[idx];
  c = sigf(gf)*c + sigf(gi)*tanhf(gc);
  g_cd[idx] = c;
  g_hd[idx] = sigf(go)*tanhf(c);
}

// ---------------- qp = h @ W2^T; grid 32 = btile(2) x ntile(16); 256 thr ----------
__global__ void __launch_bounds__(256) k_qp() {
  int bt = blockIdx.x & 1;
  int gt = blockIdx.x >> 1;
  __shared__ float sh[16][HDz];  // 32KB
  int wid = threadIdx.x >> 5, lane = threadIdx.x & 31;
  for (int bi = wid; bi < 16; bi += 8) {
    int b = bt*16 + bi;
    const float* hp = g_hd + b*HDz;
    for (int k = lane; k < HDz; k += 32) sh[bi][k] = hp[k];
  }
  __syncthreads();
  int gq = threadIdx.x & 15, bi = threadIdx.x >> 4;
  int n0 = gt*32 + gq*2;
  const float* wp = g_W2T + n0;
  const float* xr = sh[bi];
  float a0 = 0.f, a1 = 0.f;
#pragma unroll 8
  for (int k = 0; k < HDz; k++) {
    float2 w = *(const float2*)(wp + (size_t)k*HDz);
    float x = xr[k];
    a0 = fmaf(w.x, x, a0); a1 = fmaf(w.y, x, a1);
  }
  int b = bt*16 + bi;
  g_qp[b*HDz + n0]     = a0;
  g_qp[b*HDz + n0 + 1] = a1;
}

// ---------------- attention: energy, softmax, ctx, store h+ctx; grid B ------------
__global__ void __launch_bounds__(256) k_attn(int t, const float* __restrict__ vv,
                                              const int* __restrict__ lens) {
  int b = blockIdx.x;
  __shared__ float qp_s[HDz];
  __shared__ float e[Sz];
  for (int j = threadIdx.x; j < HDz; j += 256) qp_s[j] = g_qp[b*HDz + j];
  __syncthreads();

  int wid = threadIdx.x >> 5, lane = threadIdx.x & 31;
  int len = lens[b];
  for (int s = wid; s < Sz; s += 8) {
    float p = 0.f;
    const float* kp = g_kp + ((size_t)(b*Sz + s))*HDz;
    for (int j = lane; j < HDz; j += 32) p += tanhf(kp[j] + qp_s[j]) * vv[j];
#pragma unroll
    for (int o = 16; o; o >>= 1) p += __shfl_xor_sync(0xffffffffu, p, o);
    if (lane == 0) e[s] = (s < len) ? p : -1e10f;
  }
  __syncthreads();

  float m = -1e30f;
#pragma unroll
  for (int s = 0; s < Sz; s++) m = fmaxf(m, e[s]);
  float ssum = 0.f;
#pragma unroll
  for (int s = 0; s < Sz; s++) ssum += expf(e[s] - m);
  __syncthreads();
  if (threadIdx.x < Sz) e[threadIdx.x] = expf(e[threadIdx.x] - m) / ssum;
  __syncthreads();

  for (int j = threadIdx.x; j < HDz; j += 256) {
    float c = 0.f;
    const float* ep = g_enc + ((size_t)b*Sz)*(2*Hz) + j;
#pragma unroll 8
    for (int s = 0; s < Sz; s++) c = fmaf(e[s], ep[(size_t)s*(2*Hz)], c);
    g_hctx[((size_t)(b*Tz + t))*HDz + j] = g_hd[b*HDz + j] + c;
  }
}

// ---------------- fp32 SGEMM NT: C[M][N] = A[M][K] @ B[N][K]^T (+bias) ------------
// 64x64x16 tiles, 256 thr, 4x4 microtile. M%64==0, K%16==0; N guarded.
__global__ void __launch_bounds__(256) k_sgemm_nt(const float* __restrict__ A,
                                                  const float* __restrict__ Bm,
                                                  const float* __restrict__ bias,
                                                  float* __restrict__ C,
                                                  int M, int N, int K) {
  __shared__ __align__(16) float As[16][68];
  __shared__ __align__(16) float Bs[16][68];
  int n0 = blockIdx.x * 64;
  int m0 = blockIdx.y * 64;
  int tid = threadIdx.x;
  int tx = tid & 15;   // n quad
  int ty = tid >> 4;   // m quad
  float acc[4][4] = {};
  for (int k0 = 0; k0 < K; k0 += 16) {
    {
      int row = tid >> 2, c4 = tid & 3;
      float4 a = *(const float4*)(A + (size_t)(m0 + row)*K + k0 + c4*4);
      As[c4*4+0][row] = a.x; As[c4*4+1][row] = a.y;
      As[c4*4+2][row] = a.z; As[c4*4+3][row] = a.w;
      int n = n0 + row;
      float4 bv = make_float4(0.f,0.f,0.f,0.f);
      if (n < N) bv = *(const float4*)(Bm + (size_t)n*K + k0 + c4*4);
      Bs[c4*4+0][row] = bv.x; Bs[c4*4+1][row] = bv.y;
      Bs[c4*4+2][row] = bv.z; Bs[c4*4+3][row] = bv.w;
    }
    __syncthreads();
#pragma unroll
    for (int kk = 0; kk < 16; kk++) {
      float4 av = *(const float4*)&As[kk][ty*4];
      float4 bv = *(const float4*)&Bs[kk][tx*4];
      float am[4] = {av.x, av.y, av.z, av.w};
      float bn[4] = {bv.x, bv.y, bv.z, bv.w};
#pragma unroll
      for (int i = 0; i < 4; i++)
#pragma unroll
        for (int j = 0; j < 4; j++) acc[i][j] = fmaf(am[i], bn[j], acc[i][j]);
    }
    __syncthreads();
  }
#pragma unroll
  for (int i = 0; i < 4; i++) {
    int mrow = m0 + ty*4 + i;
#pragma unroll
    for (int j = 0; j < 4; j++) {
      int n = n0 + tx*4 + j;
      if (n < N) C[(size_t)mrow*N + n] = acc[i][j] + (bias ? bias[n] : 0.f);
    }
  }
}

// ---------------- loss: per-row online log-softmax NLL; grid B*T ----------------
__global__ void __launch_bounds__(256) k_loss_rows(const float* __restrict__ logits,
                                                   const int* __restrict__ oseq) {
  int row = blockIdx.x;  // b*T + t
  const float* x = logits + (size_t)row*Vz;
  float m = -1e30f, s = 0.f;
  for (int i = threadIdx.x; i < Vz; i += 256) {
    float xv = x[i];
    if (xv > m) { s = s*expf(m - xv) + 1.f; m = xv; }
    else        { s += expf(xv - m); }
  }
  __shared__ float sm[256], ss[256];
  sm[threadIdx.x] = m; ss[threadIdx.x] = s;
  __syncthreads();
  for (int o = 128; o; o >>= 1) {
    if (threadIdx.x < o) {
      float m1 = sm[threadIdx.x], s1 = ss[threadIdx.x];
      float m2 = sm[threadIdx.x+o], s2 = ss[threadIdx.x+o];
      float mm = fmaxf(m1, m2);
      sm[threadIdx.x] = mm;
      ss[threadIdx.x] = s1*expf(m1-mm) + s2*expf(m2-mm);
    }
    __syncthreads();
  }
  if (threadIdx.x == 0) {
    int tgt = oseq[row];
    float nll = sm[0] + logf(ss[0]) - x[tgt];
    float msk = (tgt != 0) ? 1.f : 0.f;
    g_rnll[row] = nll * msk;
    g_rmsk[row] = msk;
  }
}

__global__ void k_loss_reduce(float* out, int out_size) {
  __shared__ float sa[256], sb[256];
  float a = 0.f, b = 0.f;
  for (int i = threadIdx.x; i < Bz*Tz; i += 256) { a += g_rnll[i]; b += g_rmsk[i]; }
  sa[threadIdx.x] = a; sb[threadIdx.x] = b;
  __syncthreads();
  for (int o = 128; o; o >>= 1) {
    if (threadIdx.x < o) { sa[threadIdx.x] += sa[threadIdx.x+o]; sb[threadIdx.x] += sb[threadIdx.x+o]; }
    __syncthreads();
  }
  if (threadIdx.x == 0 && out_size > Bz*Tz*Vz)
    out[Bz*Tz*Vz] = sa[0] / fmaxf(sb[0], 1.f);
}

// ---------------- host orchestration ----------------
extern "C" void kernel_launch(void* const* d_in, const int* in_sizes, int n_in,
                              void* d_out, int out_size) {
  const int*   iseq = (const int*)  d_in[0];
  const int*   lens = (const int*)  d_in[1];
  const int*   oseq = (const int*)  d_in[2];
  const float* es   = (const float*)d_in[3];
  const float* Wihf = (const float*)d_in[4];
  const float* Whhf = (const float*)d_in[5];
  const float* bf   = (const float*)d_in[6];
  const float* Wihb = (const float*)d_in[7];
  const float* Whhb = (const float*)d_in[8];
  const float* bb   = (const float*)d_in[9];
  const float* et   = (const float*)d_in[10];
  const float* Wihd = (const float*)d_in[11];
  const float* Whhd = (const float*)d_in[12];
  const float* bd   = (const float*)d_in[13];
  const float* W1   = (const float*)d_in[14];
  const float* W2   = (const float*)d_in[15];
  const float* vv   = (const float*)d_in[16];
  const float* Wo   = (const float*)d_in[17];
  const float* bo   = (const float*)d_in[18];
  float* out = (float*)d_out;

  void *p_enc, *p_kp, *p_hctx;
  cudaGetSymbolAddress(&p_enc,  g_enc);
  cudaGetSymbolAddress(&p_kp,   g_kp);
  cudaGetSymbolAddress(&p_hctx, g_hctx);

  k_prep<<<2048, 256>>>(iseq, oseq, es, et, Wihf, Whhf, Wihb, Whhb, Wihd, Whhd, W2);

  for (int t = 0; t < Sz; t++) {
    k_enc_gates<<<128, 256>>>(t, bf, bb);
    k_enc_cell<<<64, 256>>>(t, lens);
  }

  // key_proj = enc @ W1^T : M=2048, N=512, K=512
  {
    dim3 grid(512/64, (Bz*Sz)/64);
    k_sgemm_nt<<<grid, 256>>>((const float*)p_enc, W1, nullptr, (float*)p_kp,
                              Bz*Sz, HDz, HDz);
  }

  for (int t = 0; t < Tz; t++) {
    k_dec_gates<<<128, 256>>>(t, bd);
    k_dec_cell<<<64, 256>>>();
    k_qp<<<32, 256>>>();
    k_attn<<<Bz, 256>>>(t, vv, lens);
  }

  // logits = hctx @ Wo^T + bo : M=1536, N=32001, K=512 -> d_out
  {
    dim3 grid((Vz + 63)/64, (Bz*Tz)/64);
    k_sgemm_nt<<<grid, 256>>>((const float*)p_hctx, Wo, bo, out,
                              Bz*Tz, Vz, HDz);
  }

  k_loss_rows<<<Bz*Tz, 256>>>(out, oseq);
  k_loss_reduce<<<1, 256>>>(out, out_size);
}

// round 9
// speedup vs baseline: 1.0118x; 1.0118x over previous
#include <cuda_runtime.h>
#include <cstdint>
#include <math.h>

#define Bz 32
#define Sz 64
#define Tz 48
#define Ez 128
#define Hz 256
#define HDz 512
#define Vz 32001
#define GEz 1024   /* 4H  */
#define GDz 2048   /* 4HD */
#define KEz 384    /* E+H  */
#define KDz 640    /* E+HD */

// ---------------- device scratch (static, allocation-free) ----------------
__device__ float g_x[Bz*Sz*Ez];
__device__ float g_di[Bz*Tz*Ez];
__device__ float g_WTf[KEz*GEz];
__device__ float g_WTb[KEz*GEz];
__device__ float g_WTd[KDz*GDz];
__device__ float g_W2T[HDz*HDz];
__device__ float g_enc[Bz*Sz*2*Hz];
__device__ float g_kp[Bz*Sz*HDz];
// ping-pong recurrent h state (read t&1, write (t+1)&1); c is thread-owned, in-place
__device__ float g_hf[2][Bz*Hz], g_hb[2][Bz*Hz];
__device__ float g_cf[Bz*Hz],    g_cb[Bz*Hz];
__device__ float g_hd[2][Bz*HDz], g_cd[Bz*HDz];
__device__ float g_qp[Bz*HDz];
__device__ float g_hctx[Bz*Tz*HDz];
__device__ float g_rnll[Bz*Tz], g_rmsk[Bz*Tz];

__device__ __forceinline__ float sigf(float x){ return 1.f/(1.f+expf(-x)); }

// ---------------- prep: embeddings, K-major weight concat+transpose, zero states ----
__global__ void k_prep(const int* __restrict__ iseq, const int* __restrict__ oseq,
                       const float* __restrict__ es, const float* __restrict__ et,
                       const float* __restrict__ Wihf, const float* __restrict__ Whhf,
                       const float* __restrict__ Wihb, const float* __restrict__ Whhb,
                       const float* __restrict__ Wihd, const float* __restrict__ Whhd,
                       const float* __restrict__ W2) {
  const int N1 = Bz*Sz*Ez;
  const int N2 = Bz*Tz*Ez;
  const int N3 = KEz*GEz;
  const int N5 = KDz*GDz;
  const int N6 = HDz*HDz;
  const int NZ = 98304;  // 2*8192 + 8192 + 2*8192 + 8192 + 2*16384 + 16384
  const int total = N1 + N2 + 2*N3 + N5 + N6 + NZ;
  for (int idx = blockIdx.x*blockDim.x + threadIdx.x; idx < total; idx += gridDim.x*blockDim.x) {
    int i = idx;
    if (i < N1) { int e = i % Ez; int bs = i / Ez;
      g_x[i] = es[(size_t)iseq[bs]*Ez + e]; continue; }
    i -= N1;
    if (i < N2) { int e = i % Ez; int bt = i / Ez; int t = bt % Tz; int b = bt / Tz;
      g_di[i] = (t==0) ? 0.f : et[(size_t)oseq[b*Tz + t-1]*Ez + e]; continue; }
    i -= N2;
    if (i < N3) { int g = i % GEz; int k = i / GEz;
      g_WTf[i] = (k < Ez) ? Wihf[g*Ez + k] : Whhf[g*Hz + (k-Ez)]; continue; }
    i -= N3;
    if (i < N3) { int g = i % GEz; int k = i / GEz;
      g_WTb[i] = (k < Ez) ? Wihb[g*Ez + k] : Whhb[g*Hz + (k-Ez)]; continue; }
    i -= N3;
    if (i < N5) { int g = i % GDz; int k = i / GDz;
      g_WTd[i] = (k < Ez) ? Wihd[g*Ez + k] : Whhd[(size_t)g*HDz + (k-Ez)]; continue; }
    i -= N5;
    if (i < N6) { int n = i % HDz; int k = i / HDz;
      g_W2T[i] = W2[n*HDz + k]; continue; }
    i -= N6;
    if (i < 16384)      ((float*)g_hf)[i] = 0.f;
    else if (i < 24576) g_cf[i-16384] = 0.f;
    else if (i < 40960) ((float*)g_hb)[i-24576] = 0.f;
    else if (i < 49152) g_cb[i-40960] = 0.f;
    else if (i < 81920) ((float*)g_hd)[i-49152] = 0.f;
    else                g_cd[i-81920] = 0.f;
  }
}

// ============ fused encoder step: gates GEMM + cell, both dirs ============
// grid 64 = bt(4: 8 batch) x jt(8: 32 j) x dir(2); 256 thr = jj(32) x bi(8)
__global__ void __launch_bounds__(256) k_enc_step(int t, const float* __restrict__ bf,
                                                  const float* __restrict__ bb,
                                                  const int* __restrict__ lens) {
  int bt  = blockIdx.x & 3;
  int jt  = (blockIdx.x >> 2) & 7;
  int dir = blockIdx.x >> 5;       // grid is exactly 64 -> dir in {0,1}
  int rd = t & 1, wr = rd ^ 1;
  int time = dir ? (Sz-1-t) : t;
  const float* WT = dir ? g_WTb : g_WTf;
  const float* hrd = dir ? g_hb[rd] : g_hf[rd];
  float*       hwr = dir ? g_hb[wr] : g_hf[wr];
  float*       cbuf = dir ? g_cb : g_cf;
  const float* bias = dir ? bb : bf;
  int j0 = jt*32;
  int tid = threadIdx.x;

  __shared__ float Xs[8][KEz];        // 12KB
  __shared__ float Ws[2][8][128];     // 8KB

  for (int idx = tid; idx < 8*KEz; idx += 256) {
    int bi = idx / KEz, k = idx - bi*KEz;
    int b = bt*8 + bi;
    Xs[bi][k] = (k < Ez) ? g_x[((size_t)(b*Sz + time))*Ez + k]
                         : hrd[b*Hz + (k - Ez)];
  }
  float r[4];
#pragma unroll
  for (int i = 0; i < 4; i++) {
    int idx = tid + i*256;
    int kk = idx >> 7, rr = idx & 127, gate = rr >> 5, jx = rr & 31;
    r[i] = WT[(size_t)kk*GEz + gate*Hz + j0 + jx];
  }
  __syncthreads();
#pragma unroll
  for (int i = 0; i < 4; i++) { int idx = tid + i*256; Ws[0][idx>>7][idx&127] = r[i]; }
  __syncthreads();

  int jj = tid & 31, bi = tid >> 5;
  float acc[4] = {0.f, 0.f, 0.f, 0.f};
  const int NT = KEz/8;
  int buf = 0;
  for (int tI = 0; tI < NT; tI++) {
    if (tI+1 < NT) {
      int k0 = (tI+1)*8;
#pragma unroll
      for (int i = 0; i < 4; i++) {
        int idx = tid + i*256;
        int kk = idx >> 7, rr = idx & 127, gate = rr >> 5, jx = rr & 31;
        r[i] = WT[(size_t)(k0+kk)*GEz + gate*Hz + j0 + jx];
      }
    }
    int kb = tI*8;
#pragma unroll
    for (int kk = 0; kk < 8; kk++) {
      float xv = Xs[bi][kb+kk];
#pragma unroll
      for (int g = 0; g < 4; g++)
        acc[g] = fmaf(Ws[buf][kk][g*32+jj], xv, acc[g]);
    }
    if (tI+1 < NT) {
#pragma unroll
      for (int i = 0; i < 4; i++) { int idx = tid + i*256; Ws[buf^1][idx>>7][idx&127] = r[i]; }
      __syncthreads();
      buf ^= 1;
    }
  }
  // in-register cell update; ping-pong h to avoid cross-block RAW race
  int j = j0 + jj;
  int b = bt*8 + bi;
  float gi = acc[0] + bias[j];
  float gf = acc[1] + bias[Hz + j];
  float gc = acc[2] + bias[2*Hz + j];
  float go = acc[3] + bias[3*Hz + j];
  bool valid = time < lens[b];
  float hprev = hrd[b*Hz + j];
  float c = cbuf[b*Hz + j];
  float cn = sigf(gf)*c + sigf(gi)*tanhf(gc);
  float hn = sigf(go)*tanhf(cn);
  bool upd = (!dir) || valid;
  if (upd) cbuf[b*Hz + j] = cn;            // c: thread-owned, in-place OK
  hwr[b*Hz + j] = upd ? hn : hprev;        // h: carried through ping-pong buffer
  g_enc[((size_t)(b*Sz+time))*(2*Hz) + dir*Hz + j] = valid ? hn : 0.f;
}

// ============ fused decoder step: gates GEMM + cell ============
// grid 64 = bt(4: 8 batch) x jt(16: 32 j); 256 thr = jj(32) x bi(8)
__global__ void __launch_bounds__(256) k_dec_step(int t, const float* __restrict__ bd) {
  int bt = blockIdx.x & 3;
  int jt = blockIdx.x >> 2;
  int rd = t & 1, wr = rd ^ 1;
  int j0 = jt*32;
  int tid = threadIdx.x;

  __shared__ float Xs[8][KDz];        // 20KB
  __shared__ float Ws[2][8][128];     // 8KB

  for (int idx = tid; idx < 8*KDz; idx += 256) {
    int bi = idx / KDz, k = idx - bi*KDz;
    int b = bt*8 + bi;
    Xs[bi][k] = (k < Ez) ? g_di[((size_t)(b*Tz + t))*Ez + k]
                         : g_hd[rd][b*HDz + (k - Ez)];
  }
  float r[4];
#pragma unroll
  for (int i = 0; i < 4; i++) {
    int idx = tid + i*256;
    int kk = idx >> 7, rr = idx & 127, gate = rr >> 5, jx = rr & 31;
    r[i] = g_WTd[(size_t)kk*GDz + gate*HDz + j0 + jx];
  }
  __syncthreads();
#pragma unroll
  for (int i = 0; i < 4; i++) { int idx = tid + i*256; Ws[0][idx>>7][idx&127] = r[i]; }
  __syncthreads();

  int jj = tid & 31, bi = tid >> 5;
  float acc[4] = {0.f, 0.f, 0.f, 0.f};
  const int NT = KDz/8;   // 80
  int buf = 0;
  for (int tI = 0; tI < NT; tI++) {
    if (tI+1 < NT) {
      int k0 = (tI+1)*8;
#pragma unroll
      for (int i = 0; i < 4; i++) {
        int idx = tid + i*256;
        int kk = idx >> 7, rr = idx & 127, gate = rr >> 5, jx = rr & 31;
        r[i] = g_WTd[(size_t)(k0+kk)*GDz + gate*HDz + j0 + jx];
      }
    }
    int kb = tI*8;
#pragma unroll
    for (int kk = 0; kk < 8; kk++) {
      float xv = Xs[bi][kb+kk];
#pragma unroll
      for (int g = 0; g < 4; g++)
        acc[g] = fmaf(Ws[buf][kk][g*32+jj], xv, acc[g]);
    }
    if (tI+1 < NT) {
#pragma unroll
      for (int i = 0; i < 4; i++) { int idx = tid + i*256; Ws[buf^1][idx>>7][idx&127] = r[i]; }
      __syncthreads();
      buf ^= 1;
    }
  }
  int j = j0 + jj;
  int b = bt*8 + bi;
  float gi = acc[0] + bd[j];
  float gf = acc[1] + bd[HDz + j];
  float gc = acc[2] + bd[2*HDz + j];
  float go = acc[3] + bd[3*HDz + j];
  float c = g_cd[b*HDz + j];
  c = sigf(gf)*c + sigf(gi)*tanhf(gc);
  g_cd[b*HDz + j] = c;
  g_hd[wr][b*HDz + j] = sigf(go)*tanhf(c);
}

// ============ qp = h @ W2^T, staged; grid 16 = bt(2) x nt(8: 64 n) ============
__global__ void __launch_bounds__(256) k_qp2(int hsel) {
  int bt = blockIdx.x & 1;
  int nt = blockIdx.x >> 1;
  int n0 = nt*64;
  int tid = threadIdx.x;
  const float* hsrc = g_hd[hsel];
  __shared__ float Xs[16][HDz];       // 32KB
  __shared__ float Ws[2][8][64];      // 4KB

  for (int idx = tid; idx < 16*HDz; idx += 256) {
    int bi = idx >> 9, k = idx & 511;
    Xs[bi][k] = hsrc[(bt*16 + bi)*HDz + k];
  }
  float r[2];
#pragma unroll
  for (int i = 0; i < 2; i++) {
    int idx = tid + i*256;
    int kk = idx >> 6, nn = idx & 63;
    r[i] = g_W2T[(size_t)kk*HDz + n0 + nn];
  }
  __syncthreads();
#pragma unroll
  for (int i = 0; i < 2; i++) { int idx = tid + i*256; Ws[0][idx>>6][idx&63] = r[i]; }
  __syncthreads();

  int nn = tid & 31, bi = tid >> 5;
  int b0 = bt*16 + bi*2;
  float acc[2][2] = {};
  const int NT = HDz/8;   // 64
  int buf = 0;
  for (int tI = 0; tI < NT; tI++) {
    if (tI+1 < NT) {
      int k0 = (tI+1)*8;
#pragma unroll
      for (int i = 0; i < 2; i++) {
        int idx = tid + i*256;
        int kk = idx >> 6, nx = idx & 63;
        r[i] = g_W2T[(size_t)(k0+kk)*HDz + n0 + nx];
      }
    }
    int kb = tI*8;
#pragma unroll
    for (int kk = 0; kk < 8; kk++) {
      float x0 = Xs[bi*2][kb+kk];
      float x1 = Xs[bi*2+1][kb+kk];
      float w0 = Ws[buf][kk][nn];
      float w1 = Ws[buf][kk][nn+32];
      acc[0][0] = fmaf(w0, x0, acc[0][0]);
      acc[0][1] = fmaf(w1, x0, acc[0][1]);
      acc[1][0] = fmaf(w0, x1, acc[1][0]);
      acc[1][1] = fmaf(w1, x1, acc[1][1]);
    }
    if (tI+1 < NT) {
#pragma unroll
      for (int i = 0; i < 2; i++) { int idx = tid + i*256; Ws[buf^1][idx>>6][idx&63] = r[i]; }
      __syncthreads();
      buf ^= 1;
    }
  }
  g_qp[b0*HDz + n0 + nn]            = acc[0][0];
  g_qp[b0*HDz + n0 + nn + 32]       = acc[0][1];
  g_qp[(b0+1)*HDz + n0 + nn]        = acc[1][0];
  g_qp[(b0+1)*HDz + n0 + nn + 32]   = acc[1][1];
}

// ---------------- attention: energy, softmax, ctx, store h+ctx; grid B ------------
__global__ void __launch_bounds__(256) k_attn(int t, int hsel, const float* __restrict__ vv,
                                              const int* __restrict__ lens) {
  int b = blockIdx.x;
  __shared__ float qp_s[HDz];
  __shared__ float e[Sz];
  for (int j = threadIdx.x; j < HDz; j += 256) qp_s[j] = g_qp[b*HDz + j];
  __syncthreads();

  int wid = threadIdx.x >> 5, lane = threadIdx.x & 31;
  int len = lens[b];
  for (int s = wid; s < Sz; s += 8) {
    float p = 0.f;
    const float* kp = g_kp + ((size_t)(b*Sz + s))*HDz;
    for (int j = lane; j < HDz; j += 32) p += tanhf(kp[j] + qp_s[j]) * vv[j];
#pragma unroll
    for (int o = 16; o; o >>= 1) p += __shfl_xor_sync(0xffffffffu, p, o);
    if (lane == 0) e[s] = (s < len) ? p : -1e10f;
  }
  __syncthreads();

  float m = -1e30f;
#pragma unroll
  for (int s = 0; s < Sz; s++) m = fmaxf(m, e[s]);
  float ssum = 0.f;
#pragma unroll
  for (int s = 0; s < Sz; s++) ssum += expf(e[s] - m);
  __syncthreads();
  if (threadIdx.x < Sz) e[threadIdx.x] = expf(e[threadIdx.x] - m) / ssum;
  __syncthreads();

  const float* hsrc = g_hd[hsel];
  for (int j = threadIdx.x; j < HDz; j += 256) {
    float c = 0.f;
    const float* ep = g_enc + ((size_t)b*Sz)*(2*Hz) + j;
#pragma unroll 8
    for (int s = 0; s < Sz; s++) c = fmaf(e[s], ep[(size_t)s*(2*Hz)], c);
    g_hctx[((size_t)(b*Tz + t))*HDz + j] = hsrc[b*HDz + j] + c;
  }
}

// ---------------- fp32 SGEMM NT 64x64 (keyproj): C = A @ B^T ----------------
__global__ void __launch_bounds__(256) k_sgemm_nt(const float* __restrict__ A,
                                                  const float* __restrict__ Bm,
                                                  const float* __restrict__ bias,
                                                  float* __restrict__ C,
                                                  int M, int N, int K) {
  __shared__ __align__(16) float As[16][68];
  __shared__ __align__(16) float Bs[16][68];
  int n0 = blockIdx.x * 64;
  int m0 = blockIdx.y * 64;
  int tid = threadIdx.x;
  int tx = tid & 15;
  int ty = tid >> 4;
  float acc[4][4] = {};
  for (int k0 = 0; k0 < K; k0 += 16) {
    {
      int row = tid >> 2, c4 = tid & 3;
      float4 a = *(const float4*)(A + (size_t)(m0 + row)*K + k0 + c4*4);
      As[c4*4+0][row] = a.x; As[c4*4+1][row] = a.y;
      As[c4*4+2][row] = a.z; As[c4*4+3][row] = a.w;
      int n = n0 + row;
      float4 bv = make_float4(0.f,0.f,0.f,0.f);
      if (n < N) bv = *(const float4*)(Bm + (size_t)n*K + k0 + c4*4);
      Bs[c4*4+0][row] = bv.x; Bs[c4*4+1][row] = bv.y;
      Bs[c4*4+2][row] = bv.z; Bs[c4*4+3][row] = bv.w;
    }
    __syncthreads();
#pragma unroll
    for (int kk = 0; kk < 16; kk++) {
      float4 av = *(const float4*)&As[kk][ty*4];
      float4 bv = *(const float4*)&Bs[kk][tx*4];
      float am[4] = {av.x, av.y, av.z, av.w};
      float bn[4] = {bv.x, bv.y, bv.z, bv.w};
#pragma unroll
      for (int i = 0; i < 4; i++)
#pragma unroll
        for (int j = 0; j < 4; j++) acc[i][j] = fmaf(am[i], bn[j], acc[i][j]);
    }
    __syncthreads();
  }
#pragma unroll
  for (int i = 0; i < 4; i++) {
    int mrow = m0 + ty*4 + i;
#pragma unroll
    for (int j = 0; j < 4; j++) {
      int n = n0 + tx*4 + j;
      if (n < N) C[(size_t)mrow*N + n] = acc[i][j] + (bias ? bias[n] : 0.f);
    }
  }
}

// ---------------- fp32 SGEMM NT 128x128, 8x8 microtile, double-buffered ------------
__global__ void __launch_bounds__(256) k_gemm128(const float* __restrict__ A,
                                                 const float* __restrict__ Bm,
                                                 const float* __restrict__ bias,
                                                 float* __restrict__ C,
                                                 int M, int N, int K) {
  __shared__ __align__(16) float As[2][16][128];
  __shared__ __align__(16) float Bs[2][16][128];
  int n0 = blockIdx.x * 128;
  int m0 = blockIdx.y * 128;
  int tid = threadIdx.x;
  int tx = tid & 15;
  int ty = tid >> 4;
  float acc[8][8] = {};
  float4 ra[2], rb[2];

#pragma unroll
  for (int i = 0; i < 2; i++) {
    int lin = tid + i*256;
    int row = lin >> 2, c4 = lin & 3;
    ra[i] = *(const float4*)(A + (size_t)(m0 + row)*K + c4*4);
    int n = n0 + row;
    rb[i] = make_float4(0.f,0.f,0.f,0.f);
    if (n < N) rb[i] = *(const float4*)(Bm + (size_t)n*K + c4*4);
  }
#pragma unroll
  for (int i = 0; i < 2; i++) {
    int lin = tid + i*256;
    int row = lin >> 2, c4 = lin & 3;
    As[0][c4*4+0][row] = ra[i].x; As[0][c4*4+1][row] = ra[i].y;
    As[0][c4*4+2][row] = ra[i].z; As[0][c4*4+3][row] = ra[i].w;
    Bs[0][c4*4+0][row] = rb[i].x; Bs[0][c4*4+1][row] = rb[i].y;
    Bs[0][c4*4+2][row] = rb[i].z; Bs[0][c4*4+3][row] = rb[i].w;
  }
  __syncthreads();

  const int NT = K / 16;
  int buf = 0;
  for (int tI = 0; tI < NT; tI++) {
    if (tI+1 < NT) {
      int k0 = (tI+1)*16;
#pragma unroll
      for (int i = 0; i < 2; i++) {
        int lin = tid + i*256;
        int row = lin >> 2, c4 = lin & 3;
        ra[i] = *(const float4*)(A + (size_t)(m0 + row)*K + k0 + c4*4);
        int n = n0 + row;
        rb[i] = make_float4(0.f,0.f,0.f,0.f);
        if (n < N) rb[i] = *(const float4*)(Bm + (size_t)n*K + k0 + c4*4);
      }
    }
#pragma unroll
    for (int kk = 0; kk < 16; kk++) {
      float a[8], b[8];
      *(float4*)&a[0] = *(const float4*)&As[buf][kk][ty*8];
      *(float4*)&a[4] = *(const float4*)&As[buf][kk][ty*8+4];
      *(float4*)&b[0] = *(const float4*)&Bs[buf][kk][tx*8];
      *(float4*)&b[4] = *(const float4*)&Bs[buf][kk][tx*8+4];
#pragma unroll
      for (int i = 0; i < 8; i++)
#pragma unroll
        for (int j = 0; j < 8; j++) acc[i][j] = fmaf(a[i], b[j], acc[i][j]);
    }
    if (tI+1 < NT) {
#pragma unroll
      for (int i = 0; i < 2; i++) {
        int lin = tid + i*256;
        int row = lin >> 2, c4 = lin & 3;
        As[buf^1][c4*4+0][row] = ra[i].x; As[buf^1][c4*4+1][row] = ra[i].y;
        As[buf^1][c4*4+2][row] = ra[i].z; As[buf^1][c4*4+3][row] = ra[i].w;
        Bs[buf^1][c4*4+0][row] = rb[i].x; Bs[buf^1][c4*4+1][row] = rb[i].y;
        Bs[buf^1][c4*4+2][row] = rb[i].z; Bs[buf^1][c4*4+3][row] = rb[i].w;
      }
      __syncthreads();
      buf ^= 1;
    }
  }
#pragma unroll
  for (int i = 0; i < 8; i++) {
    int mrow = m0 + ty*8 + i;
#pragma unroll
    for (int j = 0; j < 8; j++) {
      int n = n0 + tx*8 + j;
      if (n < N) C[(size_t)mrow*N + n] = acc[i][j] + (bias ? bias[n] : 0.f);
    }
  }
}

// ---------------- loss: per-row online log-softmax NLL; grid B*T ----------------
__global__ void __launch_bounds__(256) k_loss_rows(const float* __restrict__ logits,
                                                   const int* __restrict__ oseq) {
  int row = blockIdx.x;
  const float* x = logits + (size_t)row*Vz;
  float m = -1e30f, s = 0.f;
  for (int i = threadIdx.x; i < Vz; i += 256) {
    float xv = x[i];
    if (xv > m) { s = s*expf(m - xv) + 1.f; m = xv; }
    else        { s += expf(xv - m); }
  }
  __shared__ float sm[256], ss[256];
  sm[threadIdx.x] = m; ss[threadIdx.x] = s;
  __syncthreads();
  for (int o = 128; o; o >>= 1) {
    if (threadIdx.x < o) {
      float m1 = sm[threadIdx.x], s1 = ss[threadIdx.x];
      float m2 = sm[threadIdx.x+o], s2 = ss[threadIdx.x+o];
      float mm = fmaxf(m1, m2);
      sm[threadIdx.x] = mm;
      ss[threadIdx.x] = s1*expf(m1-mm) + s2*expf(m2-mm);
    }
    __syncthreads();
  }
  if (threadIdx.x == 0) {
    int tgt = oseq[row];
    float nll = sm[0] + logf(ss[0]) - x[tgt];
    float msk = (tgt != 0) ? 1.f : 0.f;
    g_rnll[row] = nll * msk;
    g_rmsk[row] = msk;
  }
}

__global__ void k_loss_reduce(float* out, int out_size) {
  __shared__ float sa[256], sb[256];
  float a = 0.f, b = 0.f;
  for (int i = threadIdx.x; i < Bz*Tz; i += 256) { a += g_rnll[i]; b += g_rmsk[i]; }
  sa[threadIdx.x] = a; sb[threadIdx.x] = b;
  __syncthreads();
  for (int o = 128; o; o >>= 1) {
    if (threadIdx.x < o) { sa[threadIdx.x] += sa[threadIdx.x+o]; sb[threadIdx.x] += sb[threadIdx.x+o]; }
    __syncthreads();
  }
  if (threadIdx.x == 0 && out_size > Bz*Tz*Vz)
    out[Bz*Tz*Vz] = sa[0] / fmaxf(sb[0], 1.f);
}

// ---------------- host orchestration ----------------
extern "C" void kernel_launch(void* const* d_in, const int* in_sizes, int n_in,
                              void* d_out, int out_size) {
  const int*   iseq = (const int*)  d_in[0];
  const int*   lens = (const int*)  d_in[1];
  const int*   oseq = (const int*)  d_in[2];
  const float* es   = (const float*)d_in[3];
  const float* Wihf = (const float*)d_in[4];
  const float* Whhf = (const float*)d_in[5];
  const float* bf   = (const float*)d_in[6];
  const float* Wihb = (const float*)d_in[7];
  const float* Whhb = (const float*)d_in[8];
  const float* bb   = (const float*)d_in[9];
  const float* et   = (const float*)d_in[10];
  const float* Wihd = (const float*)d_in[11];
  const float* Whhd = (const float*)d_in[12];
  const float* bd   = (const float*)d_in[13];
  const float* W1   = (const float*)d_in[14];
  const float* W2   = (const float*)d_in[15];
  const float* vv   = (const float*)d_in[16];
  const float* Wo   = (const float*)d_in[17];
  const float* bo   = (const float*)d_in[18];
  float* out = (float*)d_out;

  void *p_enc, *p_kp, *p_hctx;
  cudaGetSymbolAddress(&p_enc,  g_enc);
  cudaGetSymbolAddress(&p_kp,   g_kp);
  cudaGetSymbolAddress(&p_hctx, g_hctx);

  k_prep<<<2048, 256>>>(iseq, oseq, es, et, Wihf, Whhf, Wihb, Whhb, Wihd, Whhd, W2);

  for (int t = 0; t < Sz; t++)
    k_enc_step<<<64, 256>>>(t, bf, bb, lens);   // 64 blocks: bt(4) x jt(8) x dir(2)

  // key_proj = enc @ W1^T : M=2048, N=512, K=512
  {
    dim3 grid(512/64, (Bz*Sz)/64);
    k_sgemm_nt<<<grid, 256>>>((const float*)p_enc, W1, nullptr, (float*)p_kp,
                              Bz*Sz, HDz, HDz);
  }

  for (int t = 0; t < Tz; t++) {
    int hsel = (t + 1) & 1;                     // buffer k_dec_step wrote
    k_dec_step<<<64, 256>>>(t, bd);
    k_qp2<<<16, 256>>>(hsel);
    k_attn<<<Bz, 256>>>(t, hsel, vv, lens);
  }

  // logits = hctx @ Wo^T + bo : M=1536, N=32001, K=512 -> d_out
  {
    dim3 grid((Vz + 127)/128, (Bz*Tz)/128);
    k_gemm128<<<grid, 256>>>((const float*)p_hctx, Wo, bo, out,
                             Bz*Tz, Vz, HDz);
  }

  k_loss_rows<<<Bz*Tz, 256>>>(out, oseq);
  k_loss_reduce<<<1, 256>>>(out, out_size);
}

// round 11
// speedup vs baseline: 1.7734x; 1.7527x over previous
#include <cuda_runtime.h>
#include <cstdint>
#include <math.h>

#define Bz 32
#define Sz 64
#define Tz 48
#define Ez 128
#define Hz 256
#define HDz 512
#define Vz 32001
#define GEz 1024   /* 4H  */
#define GDz 2048   /* 4HD */

// ---------------- device scratch (static, allocation-free) ----------------
__device__ float g_x[Bz*Sz*Ez];
__device__ float g_di[Bz*Tz*Ez];
__device__ float g_gxf[Bz*Sz*GEz];   // x@Wih_f^T + bf
__device__ float g_gxb[Bz*Sz*GEz];   // x@Wih_b^T + bb
__device__ float g_gxd[Bz*Tz*GDz];   // dec_in@Wih_d^T + bd
__device__ float g_enc[Bz*Sz*2*Hz];
__device__ float g_kp[Bz*Sz*HDz];
__device__ float g_hf[2][Bz*Hz], g_hb[2][Bz*Hz];   // ping-pong h
__device__ float g_hd[2][Bz*HDz];
__device__ float g_qp[Bz*HDz];
__device__ float g_hctx[Bz*Tz*HDz];
__device__ float g_rnll[Bz*Tz], g_rmsk[Bz*Tz];

// grid barrier state (id 0 = encoder, id 1 = decoder); reset by k_prep each call
__device__ int g_bcnt[2];
__device__ volatile int g_bgen[2];

__device__ __forceinline__ float sigf(float x){ return 1.f/(1.f+expf(-x)); }

// grid-wide barrier for exactly 64 co-resident blocks
__device__ __forceinline__ void gbar(int id, int want) {
  __syncthreads();
  if (threadIdx.x == 0) {
    __threadfence();
    if (atomicAdd(&g_bcnt[id], 1) == 63) {
      g_bcnt[id] = 0;
      __threadfence();
      g_bgen[id] = want;
    } else {
      while (g_bgen[id] < want) __nanosleep(64);
    }
  }
  __syncthreads();
}

// ---------------- prep: embeddings, zero states, reset barriers ----------------
__global__ void k_prep(const int* __restrict__ iseq, const int* __restrict__ oseq,
                       const float* __restrict__ es, const float* __restrict__ et) {
  const int N1 = Bz*Sz*Ez;     // 262144
  const int N2 = Bz*Tz*Ez;     // 196608
  const int NZ = 2*Bz*Hz*2 + 2*Bz*HDz;  // hf(16384)+hb(16384)+hd(32768) = 65536
  const int total = N1 + N2 + NZ;
  if (blockIdx.x == 0 && threadIdx.x == 0) {
    g_bcnt[0] = 0; g_bcnt[1] = 0; g_bgen[0] = 0; g_bgen[1] = 0;
  }
  for (int idx = blockIdx.x*blockDim.x + threadIdx.x; idx < total; idx += gridDim.x*blockDim.x) {
    int i = idx;
    if (i < N1) { int e = i % Ez; int bs = i / Ez;
      g_x[i] = es[(size_t)iseq[bs]*Ez + e]; continue; }
    i -= N1;
    if (i < N2) { int e = i % Ez; int bt = i / Ez; int t = bt % Tz; int b = bt / Tz;
      g_di[i] = (t==0) ? 0.f : et[(size_t)oseq[b*Tz + t-1]*Ez + e]; continue; }
    i -= N2;
    if (i < 16384)      ((float*)g_hf)[i] = 0.f;
    else if (i < 32768) ((float*)g_hb)[i-16384] = 0.f;
    else                ((float*)g_hd)[i-32768] = 0.f;
  }
}

// ---------------- fp32 SGEMM NT 128x128, 8x8 microtile, double-buffered ------------
// C[M][N] = A[M][K] @ B[N][K]^T + bias.  M%128==0, K%16==0; N guarded.
__global__ void __launch_bounds__(256) k_gemm128(const float* __restrict__ A,
                                                 const float* __restrict__ Bm,
                                                 const float* __restrict__ bias,
                                                 float* __restrict__ C,
                                                 int M, int N, int K) {
  __shared__ __align__(16) float As[2][16][128];
  __shared__ __align__(16) float Bs[2][16][128];
  int n0 = blockIdx.x * 128;
  int m0 = blockIdx.y * 128;
  int tid = threadIdx.x;
  int tx = tid & 15;
  int ty = tid >> 4;
  float acc[8][8] = {};
  float4 ra[2], rb[2];

#pragma unroll
  for (int i = 0; i < 2; i++) {
    int lin = tid + i*256;
    int row = lin >> 2, c4 = lin & 3;
    ra[i] = *(const float4*)(A + (size_t)(m0 + row)*K + c4*4);
    int n = n0 + row;
    rb[i] = make_float4(0.f,0.f,0.f,0.f);
    if (n < N) rb[i] = *(const float4*)(Bm + (size_t)n*K + c4*4);
  }
#pragma unroll
  for (int i = 0; i < 2; i++) {
    int lin = tid + i*256;
    int row = lin >> 2, c4 = lin & 3;
    As[0][c4*4+0][row] = ra[i].x; As[0][c4*4+1][row] = ra[i].y;
    As[0][c4*4+2][row] = ra[i].z; As[0][c4*4+3][row] = ra[i].w;
    Bs[0][c4*4+0][row] = rb[i].x; Bs[0][c4*4+1][row] = rb[i].y;
    Bs[0][c4*4+2][row] = rb[i].z; Bs[0][c4*4+3][row] = rb[i].w;
  }
  __syncthreads();

  const int NT = K / 16;
  int buf = 0;
  for (int tI = 0; tI < NT; tI++) {
    if (tI+1 < NT) {
      int k0 = (tI+1)*16;
#pragma unroll
      for (int i = 0; i < 2; i++) {
        int lin = tid + i*256;
        int row = lin >> 2, c4 = lin & 3;
        ra[i] = *(const float4*)(A + (size_t)(m0 + row)*K + k0 + c4*4);
        int n = n0 + row;
        rb[i] = make_float4(0.f,0.f,0.f,0.f);
        if (n < N) rb[i] = *(const float4*)(Bm + (size_t)n*K + k0 + c4*4);
      }
    }
#pragma unroll
    for (int kk = 0; kk < 16; kk++) {
      float a[8], b[8];
      *(float4*)&a[0] = *(const float4*)&As[buf][kk][ty*8];
      *(float4*)&a[4] = *(const float4*)&As[buf][kk][ty*8+4];
      *(float4*)&b[0] = *(const float4*)&Bs[buf][kk][tx*8];
      *(float4*)&b[4] = *(const float4*)&Bs[buf][kk][tx*8+4];
#pragma unroll
      for (int i = 0; i < 8; i++)
#pragma unroll
        for (int j = 0; j < 8; j++) acc[i][j] = fmaf(a[i], b[j], acc[i][j]);
    }
    if (tI+1 < NT) {
#pragma unroll
      for (int i = 0; i < 2; i++) {
        int lin = tid + i*256;
        int row = lin >> 2, c4 = lin & 3;
        As[buf^1][c4*4+0][row] = ra[i].x; As[buf^1][c4*4+1][row] = ra[i].y;
        As[buf^1][c4*4+2][row] = ra[i].z; As[buf^1][c4*4+3][row] = ra[i].w;
        Bs[buf^1][c4*4+0][row] = rb[i].x; Bs[buf^1][c4*4+1][row] = rb[i].y;
        Bs[buf^1][c4*4+2][row] = rb[i].z; Bs[buf^1][c4*4+3][row] = rb[i].w;
      }
      __syncthreads();
      buf ^= 1;
    }
  }
#pragma unroll
  for (int i = 0; i < 8; i++) {
    int mrow = m0 + ty*8 + i;
#pragma unroll
    for (int j = 0; j < 8; j++) {
      int n = n0 + tx*8 + j;
      if (n < N) C[(size_t)mrow*N + n] = acc[i][j] + (bias ? bias[n] : 0.f);
    }
  }
}

// ============ persistent encoder: all 64 steps, both dirs, one launch ============
// grid 64 = dir(2) x ct(32; 8 j each). 256 thr.
// compute role:  (gc = tid&31 -> gate g=gc>>3, jj=gc&7;  kg = tid>>5: 32-k slice)
//                Whh slice (32 floats) register-stationary for the whole kernel.
// reduce role:   (rj = tid&7, rb = tid>>3) owns (b=rb, j=j0+rj); c kept in register.
__global__ void __launch_bounds__(256) k_enc_run(const float* __restrict__ Whhf,
                                                 const float* __restrict__ Whhb,
                                                 const int* __restrict__ lens) {
  extern __shared__ float sm[];
  float* h_s  = sm;               // 32*256 floats
  float* part = sm + 32*256;      // 8*32*37 floats
  int ct  = blockIdx.x & 31;
  int dir = blockIdx.x >> 5;
  int j0 = ct*8;
  int tid = threadIdx.x;
  int gc = tid & 31, kg = tid >> 5;
  int g = gc >> 3, jj = gc & 7;
  const float* Whh = dir ? Whhb : Whhf;
  const float* gx  = dir ? g_gxb : g_gxf;
  float* h0 = dir ? g_hb[0] : g_hf[0];
  float* h1 = dir ? g_hb[1] : g_hf[1];

  float4 w4[8];
  {
    const float* wrow = Whh + (size_t)(g*Hz + j0 + jj)*Hz + kg*32;
#pragma unroll
    for (int q = 0; q < 8; q++) w4[q] = *(const float4*)(wrow + q*4);
  }

  int rj = tid & 7, rb = tid >> 3;
  int len_rb = lens[rb];
  float c_reg = 0.f;

  for (int t = 0; t < Sz; t++) {
    int rd = t & 1;
    const float* hrd = rd ? h1 : h0;
    float*       hwr = rd ? h0 : h1;
    int time = dir ? (Sz-1-t) : t;

    // stage h (8192 floats)
#pragma unroll
    for (int i = 0; i < 8; i++) {
      int idx = tid + i*256;
      ((float4*)h_s)[idx] = ((const float4*)hrd)[idx];
    }
    __syncthreads();

    // partial gates GEMM: weights in regs, h broadcast from smem
    float acc[32];
#pragma unroll
    for (int b = 0; b < 32; b++) acc[b] = 0.f;
#pragma unroll
    for (int q = 0; q < 8; q++) {
      float4 w = w4[q];
      const float* hp = h_s + kg*32 + q*4;
#pragma unroll
      for (int b = 0; b < 32; b++) {
        float4 hv = *(const float4*)(hp + b*256);
        acc[b] = fmaf(w.x, hv.x, acc[b]);
        acc[b] = fmaf(w.y, hv.y, acc[b]);
        acc[b] = fmaf(w.z, hv.z, acc[b]);
        acc[b] = fmaf(w.w, hv.w, acc[b]);
      }
    }
#pragma unroll
    for (int b = 0; b < 32; b++) part[(kg*32 + gc)*37 + b] = acc[b];
    __syncthreads();

    // reduce over kg + cell update
    float s0=0.f, s1=0.f, s2=0.f, s3=0.f;
#pragma unroll
    for (int kk = 0; kk < 8; kk++) {
      s0 += part[(kk*32 +      rj)*37 + rb];
      s1 += part[(kk*32 +  8 + rj)*37 + rb];
      s2 += part[(kk*32 + 16 + rj)*37 + rb];
      s3 += part[(kk*32 + 24 + rj)*37 + rb];
    }
    int jg = j0 + rj;
    const float* gxr = gx + ((size_t)(rb*Sz + time))*GEz;
    float gi = s0 + gxr[jg];
    float gf = s1 + gxr[Hz   + jg];
    float gg = s2 + gxr[2*Hz + jg];
    float go = s3 + gxr[3*Hz + jg];
    bool valid = time < len_rb;
    float hprev = h_s[rb*256 + jg];
    float cn = sigf(gf)*c_reg + sigf(gi)*tanhf(gg);
    float hn = sigf(go)*tanhf(cn);
    bool upd = (dir == 0) || valid;
    if (upd) c_reg = cn;
    hwr[rb*Hz + jg] = upd ? hn : hprev;
    g_enc[((size_t)(rb*Sz + time))*(2*Hz) + dir*Hz + jg] = valid ? hn : 0.f;

    gbar(0, t+1);
  }
}

// ============ persistent decoder: gates+cell, qp, attention; one launch ============
// grid 64 = ct (8 j each of 512). 256 thr.
__global__ void __launch_bounds__(256) k_dec_run(const float* __restrict__ Whhd,
                                                 const float* __restrict__ W2,
                                                 const float* __restrict__ vv,
                                                 const int* __restrict__ lens) {
  extern __shared__ float sm[];
  float* h_s  = sm;               // 32*512 floats
  float* part = sm + 32*512;      // 8*32*37 floats (reused as part2 / attn scratch)
  int ct = blockIdx.x;
  int j0 = ct*8;
  int tid = threadIdx.x;
  int gc = tid & 31, kg = tid >> 5;
  int g = gc >> 3, jj = gc & 7;

  float4 w4[16];
  {
    const float* wrow = Whhd + (size_t)(g*HDz + j0 + jj)*HDz + kg*64;
#pragma unroll
    for (int q = 0; q < 16; q++) w4[q] = *(const float4*)(wrow + q*4);
  }
  int qn = tid & 7, qkg = tid >> 3;       // qp roles: 8 n x 32 kgroups(16 k)
  float4 w2r[4];
  {
    const float* w2row = W2 + (size_t)(j0 + qn)*HDz + qkg*16;
#pragma unroll
    for (int q = 0; q < 4; q++) w2r[q] = *(const float4*)(w2row + q*4);
  }

  int rj = tid & 7, rb = tid >> 3;
  float c_reg = 0.f;

  for (int t = 0; t < Tz; t++) {
    int rd = t & 1;
    const float* hrd = g_hd[rd];
    float*       hwr = g_hd[rd ^ 1];

    // ---- Phase A: gates GEMM + cell ----
#pragma unroll
    for (int i = 0; i < 16; i++) {
      int idx = tid + i*256;
      ((float4*)h_s)[idx] = ((const float4*)hrd)[idx];
    }
    __syncthreads();

#pragma unroll
    for (int half = 0; half < 2; half++) {
      float acc[16];
#pragma unroll
      for (int b = 0; b < 16; b++) acc[b] = 0.f;
#pragma unroll
      for (int q = 0; q < 16; q++) {
        float4 w = w4[q];
        const float* hp = h_s + kg*64 + q*4 + half*16*512;
#pragma unroll
        for (int b = 0; b < 16; b++) {
          float4 hv = *(const float4*)(hp + b*512);
          acc[b] = fmaf(w.x, hv.x, acc[b]);
          acc[b] = fmaf(w.y, hv.y, acc[b]);
          acc[b] = fmaf(w.z, hv.z, acc[b]);
          acc[b] = fmaf(w.w, hv.w, acc[b]);
        }
      }
#pragma unroll
      for (int b = 0; b < 16; b++) part[(kg*32 + gc)*37 + half*16 + b] = acc[b];
    }
    __syncthreads();

    {
      float s0=0.f, s1=0.f, s2=0.f, s3=0.f;
#pragma unroll
      for (int kk = 0; kk < 8; kk++) {
        s0 += part[(kk*32 +      rj)*37 + rb];
        s1 += part[(kk*32 +  8 + rj)*37 + rb];
        s2 += part[(kk*32 + 16 + rj)*37 + rb];
        s3 += part[(kk*32 + 24 + rj)*37 + rb];
      }
      int jg = j0 + rj;
      const float* gxr = g_gxd + ((size_t)(rb*Tz + t))*GDz;
      float gi = s0 + gxr[jg];
      float gf = s1 + gxr[HDz   + jg];
      float gg = s2 + gxr[2*HDz + jg];
      float go = s3 + gxr[3*HDz + jg];
      float cn = sigf(gf)*c_reg + sigf(gi)*tanhf(gg);
      c_reg = cn;
      hwr[rb*HDz + jg] = sigf(go)*tanhf(cn);
    }
    gbar(1, 3*t+1);

    // ---- Phase B: qp = h_new @ W2^T (block's 8 n-cols) ----
#pragma unroll
    for (int i = 0; i < 16; i++) {
      int idx = tid + i*256;
      ((float4*)h_s)[idx] = ((const float4*)hwr)[idx];
    }
    __syncthreads();
    {
      float acc[32];
#pragma unroll
      for (int b = 0; b < 32; b++) acc[b] = 0.f;
#pragma unroll
      for (int q = 0; q < 4; q++) {
        float4 w = w2r[q];
        const float* hp = h_s + qkg*16 + q*4;
#pragma unroll
        for (int b = 0; b < 32; b++) {
          float4 hv = *(const float4*)(hp + b*512);
          acc[b] = fmaf(w.x, hv.x, acc[b]);
          acc[b] = fmaf(w.y, hv.y, acc[b]);
          acc[b] = fmaf(w.z, hv.z, acc[b]);
          acc[b] = fmaf(w.w, hv.w, acc[b]);
        }
      }
#pragma unroll
      for (int b = 0; b < 32; b++) part[(qkg*8 + qn)*37 + b] = acc[b];
    }
    __syncthreads();
    {
      int n2 = tid & 7, b2 = tid >> 3;
      float s = 0.f;
#pragma unroll
      for (int kk = 0; kk < 32; kk++) s += part[(kk*8 + n2)*37 + b2];
      g_qp[b2*HDz + j0 + n2] = s;
    }
    gbar(1, 3*t+2);

    // ---- Phase C: attention for batch b = ct (first 32 blocks) ----
    if (ct < 32) {
      int b = ct;
      float* qp_s = part;        // 512
      float* e    = part + 512;  // 64
      for (int j = tid; j < HDz; j += 256) qp_s[j] = g_qp[b*HDz + j];
      __syncthreads();
      int wid = tid >> 5, lane = tid & 31;
      int len = lens[b];
      for (int s = wid; s < Sz; s += 8) {
        float p = 0.f;
        const float* kp = g_kp + ((size_t)(b*Sz + s))*HDz;
        for (int jx = lane; jx < HDz; jx += 32) p += tanhf(kp[jx] + qp_s[jx]) * vv[jx];
#pragma unroll
        for (int o = 16; o; o >>= 1) p += __shfl_xor_sync(0xffffffffu, p, o);
        if (lane == 0) e[s] = (s < len) ? p : -1e10f;
      }
      __syncthreads();
      float m = -1e30f;
#pragma unroll
      for (int s = 0; s < Sz; s++) m = fmaxf(m, e[s]);
      float ssum = 0.f;
#pragma unroll
      for (int s = 0; s < Sz; s++) ssum += expf(e[s] - m);
      __syncthreads();
      if (tid < Sz) e[tid] = expf(e[tid] - m) / ssum;
      __syncthreads();
      for (int jx = tid; jx < HDz; jx += 256) {
        float cx = 0.f;
        const float* ep = g_enc + ((size_t)b*Sz)*(2*Hz) + jx;
#pragma unroll 8
        for (int s = 0; s < Sz; s++) cx = fmaf(e[s], ep[(size_t)s*(2*Hz)], cx);
        g_hctx[((size_t)(b*Tz + t))*HDz + jx] = hwr[b*HDz + jx] + cx;
      }
    }
    gbar(1, 3*t+3);
  }
}

// ---------------- loss: per-row online log-softmax NLL; grid B*T ----------------
__global__ void __launch_bounds__(256) k_loss_rows(const float* __restrict__ logits,
                                                   const int* __restrict__ oseq) {
  int row = blockIdx.x;
  const float* x = logits + (size_t)row*Vz;
  float m = -1e30f, s = 0.f;
  for (int i = threadIdx.x; i < Vz; i += 256) {
    float xv = x[i];
    if (xv > m) { s = s*expf(m - xv) + 1.f; m = xv; }
    else        { s += expf(xv - m); }
  }
  __shared__ float sm[256], ss[256];
  sm[threadIdx.x] = m; ss[threadIdx.x] = s;
  __syncthreads();
  for (int o = 128; o; o >>= 1) {
    if (threadIdx.x < o) {
      float m1 = sm[threadIdx.x], s1 = ss[threadIdx.x];
      float m2 = sm[threadIdx.x+o], s2 = ss[threadIdx.x+o];
      float mm = fmaxf(m1, m2);
      sm[threadIdx.x] = mm;
      ss[threadIdx.x] = s1*expf(m1-mm) + s2*expf(m2-mm);
    }
    __syncthreads();
  }
  if (threadIdx.x == 0) {
    int tgt = oseq[row];
    float nll = sm[0] + logf(ss[0]) - x[tgt];
    float msk = (tgt != 0) ? 1.f : 0.f;
    g_rnll[row] = nll * msk;
    g_rmsk[row] = msk;
  }
}

__global__ void k_loss_reduce(float* out, int out_size) {
  __shared__ float sa[256], sb[256];
  float a = 0.f, b = 0.f;
  for (int i = threadIdx.x; i < Bz*Tz; i += 256) { a += g_rnll[i]; b += g_rmsk[i]; }
  sa[threadIdx.x] = a; sb[threadIdx.x] = b;
  __syncthreads();
  for (int o = 128; o; o >>= 1) {
    if (threadIdx.x < o) { sa[threadIdx.x] += sa[threadIdx.x+o]; sb[threadIdx.x] += sb[threadIdx.x+o]; }
    __syncthreads();
  }
  if (threadIdx.x == 0 && out_size > Bz*Tz*Vz)
    out[Bz*Tz*Vz] = sa[0] / fmaxf(sb[0], 1.f);
}

// ---------------- host orchestration ----------------
#define ENC_SMEM ((32*256 + 8*32*37)*4)
#define DEC_SMEM ((32*512 + 8*32*37)*4)

extern "C" void kernel_launch(void* const* d_in, const int* in_sizes, int n_in,
                              void* d_out, int out_size) {
  const int*   iseq = (const int*)  d_in[0];
  const int*   lens = (const int*)  d_in[1];
  const int*   oseq = (const int*)  d_in[2];
  const float* es   = (const float*)d_in[3];
  const float* Wihf = (const float*)d_in[4];
  const float* Whhf = (const float*)d_in[5];
  const float* bf   = (const float*)d_in[6];
  const float* Wihb = (const float*)d_in[7];
  const float* Whhb = (const float*)d_in[8];
  const float* bb   = (const float*)d_in[9];
  const float* et   = (const float*)d_in[10];
  const float* Wihd = (const float*)d_in[11];
  const float* Whhd = (const float*)d_in[12];
  const float* bd   = (const float*)d_in[13];
  const float* W1   = (const float*)d_in[14];
  const float* W2   = (const float*)d_in[15];
  const float* vv   = (const float*)d_in[16];
  const float* Wo   = (const float*)d_in[17];
  const float* bo   = (const float*)d_in[18];
  float* out = (float*)d_out;

  cudaFuncSetAttribute(k_enc_run, cudaFuncAttributeMaxDynamicSharedMemorySize, ENC_SMEM);
  cudaFuncSetAttribute(k_dec_run, cudaFuncAttributeMaxDynamicSharedMemorySize, DEC_SMEM);

  void *p_x, *p_di, *p_gxf, *p_gxb, *p_gxd, *p_enc, *p_kp, *p_hctx;
  cudaGetSymbolAddress(&p_x,    g_x);
  cudaGetSymbolAddress(&p_di,   g_di);
  cudaGetSymbolAddress(&p_gxf,  g_gxf);
  cudaGetSymbolAddress(&p_gxb,  g_gxb);
  cudaGetSymbolAddress(&p_gxd,  g_gxd);
  cudaGetSymbolAddress(&p_enc,  g_enc);
  cudaGetSymbolAddress(&p_kp,   g_kp);
  cudaGetSymbolAddress(&p_hctx, g_hctx);

  k_prep<<<1024, 256>>>(iseq, oseq, es, et);

  // input-gate precomputation (bias folded in)
  k_gemm128<<<dim3(GEz/128, (Bz*Sz)/128), 256>>>((const float*)p_x,  Wihf, bf,
                                                 (float*)p_gxf, Bz*Sz, GEz, Ez);
  k_gemm128<<<dim3(GEz/128, (Bz*Sz)/128), 256>>>((const float*)p_x,  Wihb, bb,
                                                 (float*)p_gxb, Bz*Sz, GEz, Ez);
  k_gemm128<<<dim3(GDz/128, (Bz*Tz)/128), 256>>>((const float*)p_di, Wihd, bd,
                                                 (float*)p_gxd, Bz*Tz, GDz, Ez);

  // persistent encoder (both directions, all 64 steps)
  k_enc_run<<<64, 256, ENC_SMEM>>>(Whhf, Whhb, lens);

  // key_proj = enc @ W1^T : M=2048, N=512, K=512
  k_gemm128<<<dim3(HDz/128, (Bz*Sz)/128), 256>>>((const float*)p_enc, W1, nullptr,
                                                 (float*)p_kp, Bz*Sz, HDz, HDz);

  // persistent decoder (gates+cell, qp, attention; all 48 steps)
  k_dec_run<<<64, 256, DEC_SMEM>>>(Whhd, W2, vv, lens);

  // logits = hctx @ Wo^T + bo : M=1536, N=32001, K=512 -> d_out
  k_gemm128<<<dim3((Vz + 127)/128, (Bz*Tz)/128), 256>>>((const float*)p_hctx, Wo, bo,
                                                        out, Bz*Tz, Vz, HDz);

  k_loss_rows<<<Bz*Tz, 256>>>(out, oseq);
  k_loss_reduce<<<1, 256>>>(out, out_size);
}

// round 12
// speedup vs baseline: 2.1574x; 1.2165x over previous
#include <cuda_runtime.h>
#include <cuda_bf16.h>
#include <cstdint>
#include <math.h>

#define Bz 32
#define Sz 64
#define Tz 48
#define Ez 128
#define Hz 256
#define HDz 512
#define Vz 32001
#define VP 32064   /* Vz padded to /64 */
#define GEz 1024   /* 4H  */
#define GDz 2048   /* 4HD */
#define KEF 1536   /* split-bf16 effective K = 3*512 */

// ---------------- device scratch (static, allocation-free) ----------------
__device__ float g_x[Bz*Sz*Ez];
__device__ float g_di[Bz*Tz*Ez];
__device__ float g_gxf[Bz*Sz*GEz];
__device__ float g_gxb[Bz*Sz*GEz];
__device__ float g_gxd[Bz*Tz*GDz];
__device__ float g_enc[Bz*Sz*2*Hz];
__device__ float g_kp[Bz*Sz*HDz];
__device__ float g_hf[2][Bz*Hz], g_hb[2][Bz*Hz];
__device__ float g_hd[2][Bz*HDz];
__device__ float g_qp[Bz*HDz];
__device__ float g_hctx[Bz*Tz*HDz];
__device__ float g_rnll[Bz*Tz], g_rmsk[Bz*Tz];
// split-bf16 operands for the logits GEMM
__device__ __nv_bfloat16 g_Bp[(size_t)VP*KEF];     // [w_hi | w_hi | w_lo]
__device__ __nv_bfloat16 g_Ap[(size_t)Bz*Tz*KEF];  // [a_hi | a_lo | a_hi]

__device__ int g_bcnt[2];
__device__ volatile int g_bgen[2];

__device__ __forceinline__ float sigf(float x){ return 1.f/(1.f+expf(-x)); }

__device__ __forceinline__ void gbar(int id, int want) {
  __syncthreads();
  if (threadIdx.x == 0) {
    __threadfence();
    if (atomicAdd(&g_bcnt[id], 1) == 63) {
      g_bcnt[id] = 0;
      __threadfence();
      g_bgen[id] = want;
    } else {
      while (g_bgen[id] < want) __nanosleep(64);
    }
  }
  __syncthreads();
}

// ---------------- prep: embeddings, zero states, reset barriers ----------------
__global__ void k_prep(const int* __restrict__ iseq, const int* __restrict__ oseq,
                       const float* __restrict__ es, const float* __restrict__ et) {
  const int N1 = Bz*Sz*Ez;
  const int N2 = Bz*Tz*Ez;
  const int NZ = 2*Bz*Hz*2 + 2*Bz*HDz;
  const int total = N1 + N2 + NZ;
  if (blockIdx.x == 0 && threadIdx.x == 0) {
    g_bcnt[0] = 0; g_bcnt[1] = 0; g_bgen[0] = 0; g_bgen[1] = 0;
  }
  for (int idx = blockIdx.x*blockDim.x + threadIdx.x; idx < total; idx += gridDim.x*blockDim.x) {
    int i = idx;
    if (i < N1) { int e = i % Ez; int bs = i / Ez;
      g_x[i] = es[(size_t)iseq[bs]*Ez + e]; continue; }
    i -= N1;
    if (i < N2) { int e = i % Ez; int bt = i / Ez; int t = bt % Tz; int b = bt / Tz;
      g_di[i] = (t==0) ? 0.f : et[(size_t)oseq[b*Tz + t-1]*Ez + e]; continue; }
    i -= N2;
    if (i < 16384)      ((float*)g_hf)[i] = 0.f;
    else if (i < 32768) ((float*)g_hb)[i-16384] = 0.f;
    else                ((float*)g_hd)[i-32768] = 0.f;
  }
}

// ---------------- split Wo into bf16 hi/lo, K-concatenated ----------------
__global__ void k_prep_w(const float* __restrict__ Wo) {
  for (int idx = blockIdx.x*blockDim.x + threadIdx.x; idx < VP*HDz; idx += gridDim.x*blockDim.x) {
    int n = idx / HDz, k = idx - (idx/HDz)*HDz;
    float w = (n < Vz) ? Wo[(size_t)n*HDz + k] : 0.f;
    __nv_bfloat16 hi = __float2bfloat16(w);
    __nv_bfloat16 lo = __float2bfloat16(w - __bfloat162float(hi));
    size_t base = (size_t)n*KEF + k;
    g_Bp[base]          = hi;
    g_Bp[base + HDz]    = hi;
    g_Bp[base + 2*HDz]  = lo;
  }
}

// ---------------- split hctx into bf16 hi/lo, K-concatenated ----------------
__global__ void k_prep_a() {
  for (int idx = blockIdx.x*blockDim.x + threadIdx.x; idx < Bz*Tz*HDz; idx += gridDim.x*blockDim.x) {
    int m = idx / HDz, k = idx - (idx/HDz)*HDz;
    float v = g_hctx[idx];
    __nv_bfloat16 hi = __float2bfloat16(v);
    __nv_bfloat16 lo = __float2bfloat16(v - __bfloat162float(hi));
    size_t base = (size_t)m*KEF + k;
    g_Ap[base]          = hi;
    g_Ap[base + HDz]    = lo;
    g_Ap[base + 2*HDz]  = hi;
  }
}

// ---------------- fp32 SGEMM NT 128x128 (gx / keyproj) ----------------
__global__ void __launch_bounds__(256) k_gemm128(const float* __restrict__ A,
                                                 const float* __restrict__ Bm,
                                                 const float* __restrict__ bias,
                                                 float* __restrict__ C,
                                                 int M, int N, int K) {
  __shared__ __align__(16) float As[2][16][128];
  __shared__ __align__(16) float Bs[2][16][128];
  int n0 = blockIdx.x * 128;
  int m0 = blockIdx.y * 128;
  int tid = threadIdx.x;
  int tx = tid & 15;
  int ty = tid >> 4;
  float acc[8][8] = {};
  float4 ra[2], rb[2];

#pragma unroll
  for (int i = 0; i < 2; i++) {
    int lin = tid + i*256;
    int row = lin >> 2, c4 = lin & 3;
    ra[i] = *(const float4*)(A + (size_t)(m0 + row)*K + c4*4);
    int n = n0 + row;
    rb[i] = make_float4(0.f,0.f,0.f,0.f);
    if (n < N) rb[i] = *(const float4*)(Bm + (size_t)n*K + c4*4);
  }
#pragma unroll
  for (int i = 0; i < 2; i++) {
    int lin = tid + i*256;
    int row = lin >> 2, c4 = lin & 3;
    As[0][c4*4+0][row] = ra[i].x; As[0][c4*4+1][row] = ra[i].y;
    As[0][c4*4+2][row] = ra[i].z; As[0][c4*4+3][row] = ra[i].w;
    Bs[0][c4*4+0][row] = rb[i].x; Bs[0][c4*4+1][row] = rb[i].y;
    Bs[0][c4*4+2][row] = rb[i].z; Bs[0][c4*4+3][row] = rb[i].w;
  }
  __syncthreads();

  const int NT = K / 16;
  int buf = 0;
  for (int tI = 0; tI < NT; tI++) {
    if (tI+1 < NT) {
      int k0 = (tI+1)*16;
#pragma unroll
      for (int i = 0; i < 2; i++) {
        int lin = tid + i*256;
        int row = lin >> 2, c4 = lin & 3;
        ra[i] = *(const float4*)(A + (size_t)(m0 + row)*K + k0 + c4*4);
        int n = n0 + row;
        rb[i] = make_float4(0.f,0.f,0.f,0.f);
        if (n < N) rb[i] = *(const float4*)(Bm + (size_t)n*K + k0 + c4*4);
      }
    }
#pragma unroll
    for (int kk = 0; kk < 16; kk++) {
      float a[8], b[8];
      *(float4*)&a[0] = *(const float4*)&As[buf][kk][ty*8];
      *(float4*)&a[4] = *(const float4*)&As[buf][kk][ty*8+4];
      *(float4*)&b[0] = *(const float4*)&Bs[buf][kk][tx*8];
      *(float4*)&b[4] = *(const float4*)&Bs[buf][kk][tx*8+4];
#pragma unroll
      for (int i = 0; i < 8; i++)
#pragma unroll
        for (int j = 0; j < 8; j++) acc[i][j] = fmaf(a[i], b[j], acc[i][j]);
    }
    if (tI+1 < NT) {
#pragma unroll
      for (int i = 0; i < 2; i++) {
        int lin = tid + i*256;
        int row = lin >> 2, c4 = lin & 3;
        As[buf^1][c4*4+0][row] = ra[i].x; As[buf^1][c4*4+1][row] = ra[i].y;
        As[buf^1][c4*4+2][row] = ra[i].z; As[buf^1][c4*4+3][row] = ra[i].w;
        Bs[buf^1][c4*4+0][row] = rb[i].x; Bs[buf^1][c4*4+1][row] = rb[i].y;
        Bs[buf^1][c4*4+2][row] = rb[i].z; Bs[buf^1][c4*4+3][row] = rb[i].w;
      }
      __syncthreads();
      buf ^= 1;
    }
  }
#pragma unroll
  for (int i = 0; i < 8; i++) {
    int mrow = m0 + ty*8 + i;
#pragma unroll
    for (int j = 0; j < 8; j++) {
      int n = n0 + tx*8 + j;
      if (n < N) C[(size_t)mrow*N + n] = acc[i][j] + (bias ? bias[n] : 0.f);
    }
  }
}

// ---------------- split-bf16 tensor-core GEMM: logits = A'@B'^T + bo ----------------
// A': [1536][KEF] bf16, B': [VP][KEF] bf16, C: [1536][Vz] fp32.
// block 128x64, 8 warps (2m x 4n), warp tile 64x16, mma.m16n8k16.
__global__ void __launch_bounds__(256) k_gemm_bf16(const float* __restrict__ bias,
                                                   float* __restrict__ C) {
  __shared__ __align__(16) __nv_bfloat16 As[2][128][40];
  __shared__ __align__(16) __nv_bfloat16 Bs[2][64][40];
  const int n0 = blockIdx.x * 64;
  const int m0 = blockIdx.y * 128;
  const int tid = threadIdx.x;
  const int warp = tid >> 5, lane = tid & 31;
  const int g = lane >> 2, tig = lane & 3;
  const int wm = warp >> 2;   // 0..1
  const int wn = warp & 3;    // 0..3
  float acc[4][2][4] = {};
  uint4 ra[2], rb;

  const int arow = tid >> 2, akq = tid & 3;   // A: rows 0..127 need 2 passes
  const int brow = tid >> 2, bkq = tid & 3;   // B: 64 rows x 4 quads = 256 exactly

  // prefetch tile 0
#pragma unroll
  for (int i = 0; i < 2; i++) {
    int lin = tid + i*256;
    int r = lin >> 2, kq = lin & 3;
    ra[i] = *(const uint4*)(g_Ap + (size_t)(m0 + r)*KEF + kq*8);
  }
  rb = *(const uint4*)(g_Bp + (size_t)(n0 + brow)*KEF + bkq*8);
#pragma unroll
  for (int i = 0; i < 2; i++) {
    int lin = tid + i*256;
    int r = lin >> 2, kq = lin & 3;
    *(uint4*)&As[0][r][kq*8] = ra[i];
  }
  *(uint4*)&Bs[0][brow][bkq*8] = rb;
  __syncthreads();

  const int KT = KEF / 32;  // 48
  int buf = 0;
  for (int tI = 0; tI < KT; tI++) {
    if (tI+1 < KT) {
      int k0 = (tI+1)*32;
#pragma unroll
      for (int i = 0; i < 2; i++) {
        int lin = tid + i*256;
        int r = lin >> 2, kq = lin & 3;
        ra[i] = *(const uint4*)(g_Ap + (size_t)(m0 + r)*KEF + k0 + kq*8);
      }
      rb = *(const uint4*)(g_Bp + (size_t)(n0 + brow)*KEF + k0 + bkq*8);
    }
    const uint32_t* A32 = (const uint32_t*)As[buf];
    const uint32_t* B32 = (const uint32_t*)Bs[buf];
#pragma unroll
    for (int s = 0; s < 2; s++) {
      int ko = s*8;
      uint32_t a0[4], a1[4], a2[4], a3[4];
#pragma unroll
      for (int mi = 0; mi < 4; mi++) {
        int r = wm*64 + mi*16;
        a0[mi] = A32[(r+g)*20   + ko + tig];
        a1[mi] = A32[(r+g+8)*20 + ko + tig];
        a2[mi] = A32[(r+g)*20   + ko + tig + 4];
        a3[mi] = A32[(r+g+8)*20 + ko + tig + 4];
      }
      uint32_t b0[2], b1[2];
#pragma unroll
      for (int ni = 0; ni < 2; ni++) {
        int r = wn*16 + ni*8;
        b0[ni] = B32[(r+g)*20 + ko + tig];
        b1[ni] = B32[(r+g)*20 + ko + tig + 4];
      }
#pragma unroll
      for (int mi = 0; mi < 4; mi++)
#pragma unroll
        for (int ni = 0; ni < 2; ni++)
          asm volatile("mma.sync.aligned.m16n8k16.row.col.f32.bf16.bf16.f32 "
                       "{%0,%1,%2,%3}, {%4,%5,%6,%7}, {%8,%9}, {%0,%1,%2,%3};"
                       : "+f"(acc[mi][ni][0]), "+f"(acc[mi][ni][1]),
                         "+f"(acc[mi][ni][2]), "+f"(acc[mi][ni][3])
                       : "r"(a0[mi]), "r"(a1[mi]), "r"(a2[mi]), "r"(a3[mi]),
                         "r"(b0[ni]), "r"(b1[ni]));
    }
    if (tI+1 < KT) {
      __syncthreads();
#pragma unroll
      for (int i = 0; i < 2; i++) {
        int lin = tid + i*256;
        int r = lin >> 2, kq = lin & 3;
        *(uint4*)&As[buf^1][r][kq*8] = ra[i];
      }
      *(uint4*)&Bs[buf^1][brow][bkq*8] = rb;
      __syncthreads();
      buf ^= 1;
    }
  }

  // epilogue: fp32 + bias
#pragma unroll
  for (int mi = 0; mi < 4; mi++) {
    int r = m0 + wm*64 + mi*16;
#pragma unroll
    for (int ni = 0; ni < 2; ni++) {
      int col = n0 + wn*16 + ni*8 + 2*tig;
      if (col < Vz) {
        float b0v = bias[col];
        C[(size_t)(r+g)*Vz + col]   = acc[mi][ni][0] + b0v;
        C[(size_t)(r+g+8)*Vz + col] = acc[mi][ni][2] + b0v;
      }
      if (col + 1 < Vz) {
        float b1v = bias[col+1];
        C[(size_t)(r+g)*Vz + col+1]   = acc[mi][ni][1] + b1v;
        C[(size_t)(r+g+8)*Vz + col+1] = acc[mi][ni][3] + b1v;
      }
    }
  }
}

// ============ persistent encoder ============
__global__ void __launch_bounds__(256) k_enc_run(const float* __restrict__ Whhf,
                                                 const float* __restrict__ Whhb,
                                                 const int* __restrict__ lens) {
  extern __shared__ float sm[];
  float* h_s  = sm;
  float* part = sm + 32*256;
  int ct  = blockIdx.x & 31;
  int dir = blockIdx.x >> 5;
  int j0 = ct*8;
  int tid = threadIdx.x;
  int gc = tid & 31, kg = tid >> 5;
  int g = gc >> 3, jj = gc & 7;
  const float* Whh = dir ? Whhb : Whhf;
  const float* gx  = dir ? g_gxb : g_gxf;
  float* h0 = dir ? g_hb[0] : g_hf[0];
  float* h1 = dir ? g_hb[1] : g_hf[1];

  float4 w4[8];
  {
    const float* wrow = Whh + (size_t)(g*Hz + j0 + jj)*Hz + kg*32;
#pragma unroll
    for (int q = 0; q < 8; q++) w4[q] = *(const float4*)(wrow + q*4);
  }

  int rj = tid & 7, rb = tid >> 3;
  int len_rb = lens[rb];
  float c_reg = 0.f;

  for (int t = 0; t < Sz; t++) {
    int rd = t & 1;
    const float* hrd = rd ? h1 : h0;
    float*       hwr = rd ? h0 : h1;
    int time = dir ? (Sz-1-t) : t;

#pragma unroll
    for (int i = 0; i < 8; i++) {
      int idx = tid + i*256;
      ((float4*)h_s)[idx] = ((const float4*)hrd)[idx];
    }
    __syncthreads();

    float acc[32];
#pragma unroll
    for (int b = 0; b < 32; b++) acc[b] = 0.f;
#pragma unroll
    for (int q = 0; q < 8; q++) {
      float4 w = w4[q];
      const float* hp = h_s + kg*32 + q*4;
#pragma unroll
      for (int b = 0; b < 32; b++) {
        float4 hv = *(const float4*)(hp + b*256);
        acc[b] = fmaf(w.x, hv.x, acc[b]);
        acc[b] = fmaf(w.y, hv.y, acc[b]);
        acc[b] = fmaf(w.z, hv.z, acc[b]);
        acc[b] = fmaf(w.w, hv.w, acc[b]);
      }
    }
#pragma unroll
    for (int b = 0; b < 32; b++) part[(kg*32 + gc)*37 + b] = acc[b];
    __syncthreads();

    float s0=0.f, s1=0.f, s2=0.f, s3=0.f;
#pragma unroll
    for (int kk = 0; kk < 8; kk++) {
      s0 += part[(kk*32 +      rj)*37 + rb];
      s1 += part[(kk*32 +  8 + rj)*37 + rb];
      s2 += part[(kk*32 + 16 + rj)*37 + rb];
      s3 += part[(kk*32 + 24 + rj)*37 + rb];
    }
    int jg = j0 + rj;
    const float* gxr = gx + ((size_t)(rb*Sz + time))*GEz;
    float gi = s0 + gxr[jg];
    float gf = s1 + gxr[Hz   + jg];
    float gg = s2 + gxr[2*Hz + jg];
    float go = s3 + gxr[3*Hz + jg];
    bool valid = time < len_rb;
    float hprev = h_s[rb*256 + jg];
    float cn = sigf(gf)*c_reg + sigf(gi)*tanhf(gg);
    float hn = sigf(go)*tanhf(cn);
    bool upd = (dir == 0) || valid;
    if (upd) c_reg = cn;
    hwr[rb*Hz + jg] = upd ? hn : hprev;
    g_enc[((size_t)(rb*Sz + time))*(2*Hz) + dir*Hz + jg] = valid ? hn : 0.f;

    gbar(0, t+1);
  }
}

// ============ persistent decoder ============
__global__ void __launch_bounds__(256) k_dec_run(const float* __restrict__ Whhd,
                                                 const float* __restrict__ W2,
                                                 const float* __restrict__ vv,
                                                 const int* __restrict__ lens) {
  extern __shared__ float sm[];
  float* h_s  = sm;
  float* part = sm + 32*512;
  int ct = blockIdx.x;
  int j0 = ct*8;
  int tid = threadIdx.x;
  int gc = tid & 31, kg = tid >> 5;
  int g = gc >> 3, jj = gc & 7;

  float4 w4[16];
  {
    const float* wrow = Whhd + (size_t)(g*HDz + j0 + jj)*HDz + kg*64;
#pragma unroll
    for (int q = 0; q < 16; q++) w4[q] = *(const float4*)(wrow + q*4);
  }
  int qn = tid & 7, qkg = tid >> 3;
  float4 w2r[4];
  {
    const float* w2row = W2 + (size_t)(j0 + qn)*HDz + qkg*16;
#pragma unroll
    for (int q = 0; q < 4; q++) w2r[q] = *(const float4*)(w2row + q*4);
  }

  int rj = tid & 7, rb = tid >> 3;
  float c_reg = 0.f;

  for (int t = 0; t < Tz; t++) {
    int rd = t & 1;
    const float* hrd = g_hd[rd];
    float*       hwr = g_hd[rd ^ 1];

#pragma unroll
    for (int i = 0; i < 16; i++) {
      int idx = tid + i*256;
      ((float4*)h_s)[idx] = ((const float4*)hrd)[idx];
    }
    __syncthreads();

#pragma unroll
    for (int half = 0; half < 2; half++) {
      float acc[16];
#pragma unroll
      for (int b = 0; b < 16; b++) acc[b] = 0.f;
#pragma unroll
      for (int q = 0; q < 16; q++) {
        float4 w = w4[q];
        const float* hp = h_s + kg*64 + q*4 + half*16*512;
#pragma unroll
        for (int b = 0; b < 16; b++) {
          float4 hv = *(const float4*)(hp + b*512);
          acc[b] = fmaf(w.x, hv.x, acc[b]);
          acc[b] = fmaf(w.y, hv.y, acc[b]);
          acc[b] = fmaf(w.z, hv.z, acc[b]);
          acc[b] = fmaf(w.w, hv.w, acc[b]);
        }
      }
#pragma unroll
      for (int b = 0; b < 16; b++) part[(kg*32 + gc)*37 + half*16 + b] = acc[b];
    }
    __syncthreads();

    {
      float s0=0.f, s1=0.f, s2=0.f, s3=0.f;
#pragma unroll
      for (int kk = 0; kk < 8; kk++) {
        s0 += part[(kk*32 +      rj)*37 + rb];
        s1 += part[(kk*32 +  8 + rj)*37 + rb];
        s2 += part[(kk*32 + 16 + rj)*37 + rb];
        s3 += part[(kk*32 + 24 + rj)*37 + rb];
      }
      int jg = j0 + rj;
      const float* gxr = g_gxd + ((size_t)(rb*Tz + t))*GDz;
      float gi = s0 + gxr[jg];
      float gf = s1 + gxr[HDz   + jg];
      float gg = s2 + gxr[2*HDz + jg];
      float go = s3 + gxr[3*HDz + jg];
      float cn = sigf(gf)*c_reg + sigf(gi)*tanhf(gg);
      c_reg = cn;
      hwr[rb*HDz + jg] = sigf(go)*tanhf(cn);
    }
    gbar(1, 3*t+1);

#pragma unroll
    for (int i = 0; i < 16; i++) {
      int idx = tid + i*256;
      ((float4*)h_s)[idx] = ((const float4*)hwr)[idx];
    }
    __syncthreads();
    {
      float acc[32];
#pragma unroll
      for (int b = 0; b < 32; b++) acc[b] = 0.f;
#pragma unroll
      for (int q = 0; q < 4; q++) {
        float4 w = w2r[q];
        const float* hp = h_s + qkg*16 + q*4;
#pragma unroll
        for (int b = 0; b < 32; b++) {
          float4 hv = *(const float4*)(hp + b*512);
          acc[b] = fmaf(w.x, hv.x, acc[b]);
          acc[b] = fmaf(w.y, hv.y, acc[b]);
          acc[b] = fmaf(w.z, hv.z, acc[b]);
          acc[b] = fmaf(w.w, hv.w, acc[b]);
        }
      }
#pragma unroll
      for (int b = 0; b < 32; b++) part[(qkg*8 + qn)*37 + b] = acc[b];
    }
    __syncthreads();
    {
      int n2 = tid & 7, b2 = tid >> 3;
      float s = 0.f;
#pragma unroll
      for (int kk = 0; kk < 32; kk++) s += part[(kk*8 + n2)*37 + b2];
      g_qp[b2*HDz + j0 + n2] = s;
    }
    gbar(1, 3*t+2);

    if (ct < 32) {
      int b = ct;
      float* qp_s = part;
      float* e    = part + 512;
      for (int j = tid; j < HDz; j += 256) qp_s[j] = g_qp[b*HDz + j];
      __syncthreads();
      int wid = tid >> 5, lane = tid & 31;
      int len = lens[b];
      for (int s = wid; s < Sz; s += 8) {
        float p = 0.f;
        const float* kp = g_kp + ((size_t)(b*Sz + s))*HDz;
        for (int jx = lane; jx < HDz; jx += 32) p += tanhf(kp[jx] + qp_s[jx]) * vv[jx];
#pragma unroll
        for (int o = 16; o; o >>= 1) p += __shfl_xor_sync(0xffffffffu, p, o);
        if (lane == 0) e[s] = (s < len) ? p : -1e10f;
      }
      __syncthreads();
      float m = -1e30f;
#pragma unroll
      for (int s = 0; s < Sz; s++) m = fmaxf(m, e[s]);
      float ssum = 0.f;
#pragma unroll
      for (int s = 0; s < Sz; s++) ssum += expf(e[s] - m);
      __syncthreads();
      if (tid < Sz) e[tid] = expf(e[tid] - m) / ssum;
      __syncthreads();
      for (int jx = tid; jx < HDz; jx += 256) {
        float cx = 0.f;
        const float* ep = g_enc + ((size_t)b*Sz)*(2*Hz) + jx;
#pragma unroll 8
        for (int s = 0; s < Sz; s++) cx = fmaf(e[s], ep[(size_t)s*(2*Hz)], cx);
        g_hctx[((size_t)(b*Tz + t))*HDz + jx] = hwr[b*HDz + jx] + cx;
      }
    }
    gbar(1, 3*t+3);
  }
}

// ---------------- loss: two-pass max + FMA-pipe poly-exp sum; grid B*T ----------------
__global__ void __launch_bounds__(256) k_loss_rows(const float* __restrict__ logits,
                                                   const int* __restrict__ oseq) {
  int row = blockIdx.x;
  const float* x = logits + (size_t)row*Vz;
  __shared__ float red[256];

  float m = -1e30f;
  for (int i = threadIdx.x; i < Vz; i += 256) m = fmaxf(m, x[i]);
  red[threadIdx.x] = m;
  __syncthreads();
  for (int o = 128; o; o >>= 1) {
    if (threadIdx.x < o) red[threadIdx.x] = fmaxf(red[threadIdx.x], red[threadIdx.x+o]);
    __syncthreads();
  }
  m = red[0];
  __syncthreads();

  float s = 0.f;
  for (int i = threadIdx.x; i < Vz; i += 256) {
    float y = (x[i] - m) * 1.4426950408889634f;       // log2(e); y <= 0
    float t = y + 12582912.0f;                        // 2^23 + 2^22 magic round
    int   n = (__float_as_int(t) & 0x7FFFFF) - 0x400000;
    float f = y - (t - 12582912.0f);                  // f in [-0.5, 0.5]
    float p = 1.f + f*(0.6931471806f + f*(0.2402265069f + f*(0.0555041087f +
              f*(0.0096181291f + f*0.0013333558f))));
    n = max(n, -126);
    s += p * __int_as_float((n + 127) << 23);
  }
  red[threadIdx.x] = s;
  __syncthreads();
  for (int o = 128; o; o >>= 1) {
    if (threadIdx.x < o) red[threadIdx.x] += red[threadIdx.x+o];
    __syncthreads();
  }
  if (threadIdx.x == 0) {
    int tgt = oseq[row];
    float nll = m + logf(red[0]) - x[tgt];
    float msk = (tgt != 0) ? 1.f : 0.f;
    g_rnll[row] = nll * msk;
    g_rmsk[row] = msk;
  }
}

__global__ void k_loss_reduce(float* out, int out_size) {
  __shared__ float sa[256], sb[256];
  float a = 0.f, b = 0.f;
  for (int i = threadIdx.x; i < Bz*Tz; i += 256) { a += g_rnll[i]; b += g_rmsk[i]; }
  sa[threadIdx.x] = a; sb[threadIdx.x] = b;
  __syncthreads();
  for (int o = 128; o; o >>= 1) {
    if (threadIdx.x < o) { sa[threadIdx.x] += sa[threadIdx.x+o]; sb[threadIdx.x] += sb[threadIdx.x+o]; }
    __syncthreads();
  }
  if (threadIdx.x == 0 && out_size > Bz*Tz*Vz)
    out[Bz*Tz*Vz] = sa[0] / fmaxf(sb[0], 1.f);
}

// ---------------- host orchestration ----------------
#define ENC_SMEM ((32*256 + 8*32*37)*4)
#define DEC_SMEM ((32*512 + 8*32*37)*4)

extern "C" void kernel_launch(void* const* d_in, const int* in_sizes, int n_in,
                              void* d_out, int out_size) {
  const int*   iseq = (const int*)  d_in[0];
  const int*   lens = (const int*)  d_in[1];
  const int*   oseq = (const int*)  d_in[2];
  const float* es   = (const float*)d_in[3];
  const float* Wihf = (const float*)d_in[4];
  const float* Whhf = (const float*)d_in[5];
  const float* bf   = (const float*)d_in[6];
  const float* Wihb = (const float*)d_in[7];
  const float* Whhb = (const float*)d_in[8];
  const float* bb   = (const float*)d_in[9];
  const float* et   = (const float*)d_in[10];
  const float* Wihd = (const float*)d_in[11];
  const float* Whhd = (const float*)d_in[12];
  const float* bd   = (const float*)d_in[13];
  const float* W1   = (const float*)d_in[14];
  const float* W2   = (const float*)d_in[15];
  const float* vv   = (const float*)d_in[16];
  const float* Wo   = (const float*)d_in[17];
  const float* bo   = (const float*)d_in[18];
  float* out = (float*)d_out;

  cudaFuncSetAttribute(k_enc_run, cudaFuncAttributeMaxDynamicSharedMemorySize, ENC_SMEM);
  cudaFuncSetAttribute(k_dec_run, cudaFuncAttributeMaxDynamicSharedMemorySize, DEC_SMEM);

  void *p_x, *p_di, *p_gxf, *p_gxb, *p_gxd, *p_enc, *p_kp;
  cudaGetSymbolAddress(&p_x,    g_x);
  cudaGetSymbolAddress(&p_di,   g_di);
  cudaGetSymbolAddress(&p_gxf,  g_gxf);
  cudaGetSymbolAddress(&p_gxb,  g_gxb);
  cudaGetSymbolAddress(&p_gxd,  g_gxd);
  cudaGetSymbolAddress(&p_enc,  g_enc);
  cudaGetSymbolAddress(&p_kp,   g_kp);

  k_prep<<<1024, 256>>>(iseq, oseq, es, et);
  k_prep_w<<<2048, 256>>>(Wo);

  k_gemm128<<<dim3(GEz/128, (Bz*Sz)/128), 256>>>((const float*)p_x,  Wihf, bf,
                                                 (float*)p_gxf, Bz*Sz, GEz, Ez);
  k_gemm128<<<dim3(GEz/128, (Bz*Sz)/128), 256>>>((const float*)p_x,  Wihb, bb,
                                                 (float*)p_gxb, Bz*Sz, GEz, Ez);
  k_gemm128<<<dim3(GDz/128, (Bz*Tz)/128), 256>>>((const float*)p_di, Wihd, bd,
                                                 (float*)p_gxd, Bz*Tz, GDz, Ez);

  k_enc_run<<<64, 256, ENC_SMEM>>>(Whhf, Whhb, lens);

  k_gemm128<<<dim3(HDz/128, (Bz*Sz)/128), 256>>>((const float*)p_enc, W1, nullptr,
                                                 (float*)p_kp, Bz*Sz, HDz, HDz);

  k_dec_run<<<64, 256, DEC_SMEM>>>(Whhd, W2, vv, lens);

  k_prep_a<<<512, 256>>>();

  // logits = hctx @ Wo^T + bo via split-bf16 tensor cores
  k_gemm_bf16<<<dim3(VP/64, (Bz*Tz)/128), 256>>>(bo, out);

  k_loss_rows<<<Bz*Tz, 256>>>(out, oseq);
  k_loss_reduce<<<1, 256>>>(out, out_size);
}

// round 15
// speedup vs baseline: 2.3691x; 1.0981x over previous
#include <cuda_runtime.h>
#include <cuda_bf16.h>
#include <cstdint>
#include <math.h>

#define Bz 32
#define Sz 64
#define Tz 48
#define Ez 128
#define Hz 256
#define HDz 512
#define Vz 32001
#define VP2 32128  /* Vz padded to /128 */
#define GEz 1024   /* 4H  */
#define GDz 2048   /* 4HD */
#define KEF 1536   /* split-bf16 effective K = 3*512 */

// ---------------- device scratch (static, allocation-free) ----------------
__device__ float g_x[Bz*Sz*Ez];
__device__ float g_di[Bz*Tz*Ez];
__device__ float g_gxf[Bz*Sz*GEz];
__device__ float g_gxb[Bz*Sz*GEz];
__device__ float g_gxd[Bz*Tz*GDz];
__device__ float g_enc[Bz*Sz*2*Hz];
__device__ float g_kp[Bz*Sz*HDz];
__device__ float g_hf[2][Bz*Hz], g_hb[2][Bz*Hz];
__device__ float g_hd[2][Bz*HDz];
__device__ float g_qp[Bz*HDz];
__device__ float g_hctx[Bz*Tz*HDz];
__device__ float g_rnll[Bz*Tz], g_rmsk[Bz*Tz];
__device__ __nv_bfloat16 g_Bp[(size_t)VP2*KEF];    // [w_hi | w_hi | w_lo]
__device__ __nv_bfloat16 g_Ap[(size_t)Bz*Tz*KEF];  // [a_hi | a_lo | a_hi]

__device__ int g_bcnt[2];
__device__ volatile int g_bgen[2];

__device__ __forceinline__ float sigf(float x){ return 1.f/(1.f+expf(-x)); }

__device__ __forceinline__ void gbar(int id, int want) {
  __syncthreads();
  if (threadIdx.x == 0) {
    __threadfence();
    if (atomicAdd(&g_bcnt[id], 1) == 63) {
      g_bcnt[id] = 0;
      __threadfence();
      g_bgen[id] = want;
    } else {
      while (g_bgen[id] < want) __nanosleep(64);
    }
  }
  __syncthreads();
}

// ---------------- prep: embeddings, zero states, reset barriers ----------------
__global__ void k_prep(const int* __restrict__ iseq, const int* __restrict__ oseq,
                       const float* __restrict__ es, const float* __restrict__ et) {
  const int N1 = Bz*Sz*Ez;
  const int N2 = Bz*Tz*Ez;
  const int NZ = 2*Bz*Hz*2 + 2*Bz*HDz;
  const int total = N1 + N2 + NZ;
  if (blockIdx.x == 0 && threadIdx.x == 0) {
    g_bcnt[0] = 0; g_bcnt[1] = 0; g_bgen[0] = 0; g_bgen[1] = 0;
  }
  for (int idx = blockIdx.x*blockDim.x + threadIdx.x; idx < total; idx += gridDim.x*blockDim.x) {
    int i = idx;
    if (i < N1) { int e = i % Ez; int bs = i / Ez;
      g_x[i] = es[(size_t)iseq[bs]*Ez + e]; continue; }
    i -= N1;
    if (i < N2) { int e = i % Ez; int bt = i / Ez; int t = bt % Tz; int b = bt / Tz;
      g_di[i] = (t==0) ? 0.f : et[(size_t)oseq[b*Tz + t-1]*Ez + e]; continue; }
    i -= N2;
    if (i < 16384)      ((float*)g_hf)[i] = 0.f;
    else if (i < 32768) ((float*)g_hb)[i-16384] = 0.f;
    else                ((float*)g_hd)[i-32768] = 0.f;
  }
}

// ---------------- split Wo into bf16 hi/lo, K-concatenated ----------------
__global__ void k_prep_w(const float* __restrict__ Wo) {
  for (size_t idx = (size_t)blockIdx.x*blockDim.x + threadIdx.x; idx < (size_t)VP2*HDz;
       idx += (size_t)gridDim.x*blockDim.x) {
    int n = (int)(idx / HDz), k = (int)(idx - (size_t)n*HDz);
    float w = (n < Vz) ? Wo[(size_t)n*HDz + k] : 0.f;
    __nv_bfloat16 hi = __float2bfloat16(w);
    __nv_bfloat16 lo = __float2bfloat16(w - __bfloat162float(hi));
    size_t base = (size_t)n*KEF + k;
    g_Bp[base]          = hi;
    g_Bp[base + HDz]    = hi;
    g_Bp[base + 2*HDz]  = lo;
  }
}

// ---------------- split hctx into bf16 hi/lo, K-concatenated ----------------
__global__ void k_prep_a() {
  for (int idx = blockIdx.x*blockDim.x + threadIdx.x; idx < Bz*Tz*HDz; idx += gridDim.x*blockDim.x) {
    int m = idx / HDz, k = idx - (idx/HDz)*HDz;
    float v = g_hctx[idx];
    __nv_bfloat16 hi = __float2bfloat16(v);
    __nv_bfloat16 lo = __float2bfloat16(v - __bfloat162float(hi));
    size_t base = (size_t)m*KEF + k;
    g_Ap[base]          = hi;
    g_Ap[base + HDz]    = lo;
    g_Ap[base + 2*HDz]  = hi;
  }
}

// ---------------- fp32 SGEMM NT 128x128 (gx / keyproj) ----------------
__global__ void __launch_bounds__(256) k_gemm128(const float* __restrict__ A,
                                                 const float* __restrict__ Bm,
                                                 const float* __restrict__ bias,
                                                 float* __restrict__ C,
                                                 int M, int N, int K) {
  __shared__ __align__(16) float As[2][16][128];
  __shared__ __align__(16) float Bs[2][16][128];
  int n0 = blockIdx.x * 128;
  int m0 = blockIdx.y * 128;
  int tid = threadIdx.x;
  int tx = tid & 15;
  int ty = tid >> 4;
  float acc[8][8] = {};
  float4 ra[2], rb[2];

#pragma unroll
  for (int i = 0; i < 2; i++) {
    int lin = tid + i*256;
    int row = lin >> 2, c4 = lin & 3;
    ra[i] = *(const float4*)(A + (size_t)(m0 + row)*K + c4*4);
    int n = n0 + row;
    rb[i] = make_float4(0.f,0.f,0.f,0.f);
    if (n < N) rb[i] = *(const float4*)(Bm + (size_t)n*K + c4*4);
  }
#pragma unroll
  for (int i = 0; i < 2; i++) {
    int lin = tid + i*256;
    int row = lin >> 2, c4 = lin & 3;
    As[0][c4*4+0][row] = ra[i].x; As[0][c4*4+1][row] = ra[i].y;
    As[0][c4*4+2][row] = ra[i].z; As[0][c4*4+3][row] = ra[i].w;
    Bs[0][c4*4+0][row] = rb[i].x; Bs[0][c4*4+1][row] = rb[i].y;
    Bs[0][c4*4+2][row] = rb[i].z; Bs[0][c4*4+3][row] = rb[i].w;
  }
  __syncthreads();

  const int NT = K / 16;
  int buf = 0;
  for (int tI = 0; tI < NT; tI++) {
    if (tI+1 < NT) {
      int k0 = (tI+1)*16;
#pragma unroll
      for (int i = 0; i < 2; i++) {
        int lin = tid + i*256;
        int row = lin >> 2, c4 = lin & 3;
        ra[i] = *(const float4*)(A + (size_t)(m0 + row)*K + k0 + c4*4);
        int n = n0 + row;
        rb[i] = make_float4(0.f,0.f,0.f,0.f);
        if (n < N) rb[i] = *(const float4*)(Bm + (size_t)n*K + k0 + c4*4);
      }
    }
#pragma unroll
    for (int kk = 0; kk < 16; kk++) {
      float a[8], b[8];
      *(float4*)&a[0] = *(const float4*)&As[buf][kk][ty*8];
      *(float4*)&a[4] = *(const float4*)&As[buf][kk][ty*8+4];
      *(float4*)&b[0] = *(const float4*)&Bs[buf][kk][tx*8];
      *(float4*)&b[4] = *(const float4*)&Bs[buf][kk][tx*8+4];
#pragma unroll
      for (int i = 0; i < 8; i++)
#pragma unroll
        for (int j = 0; j < 8; j++) acc[i][j] = fmaf(a[i], b[j], acc[i][j]);
    }
    if (tI+1 < NT) {
#pragma unroll
      for (int i = 0; i < 2; i++) {
        int lin = tid + i*256;
        int row = lin >> 2, c4 = lin & 3;
        As[buf^1][c4*4+0][row] = ra[i].x; As[buf^1][c4*4+1][row] = ra[i].y;
        As[buf^1][c4*4+2][row] = ra[i].z; As[buf^1][c4*4+3][row] = ra[i].w;
        Bs[buf^1][c4*4+0][row] = rb[i].x; Bs[buf^1][c4*4+1][row] = rb[i].y;
        Bs[buf^1][c4*4+2][row] = rb[i].z; Bs[buf^1][c4*4+3][row] = rb[i].w;
      }
      __syncthreads();
      buf ^= 1;
    }
  }
#pragma unroll
  for (int i = 0; i < 8; i++) {
    int mrow = m0 + ty*8 + i;
#pragma unroll
    for (int j = 0; j < 8; j++) {
      int n = n0 + tx*8 + j;
      if (n < N) C[(size_t)mrow*N + n] = acc[i][j] + (bias ? bias[n] : 0.f);
    }
  }
}

// ---------------- split-bf16 mma.sync GEMM: logits = A'@B'^T + bo ----------------
// A': [1536][KEF] bf16, B': [VP2][KEF] bf16, C: [1536][Vz] fp32.
// block 128(M) x 128(N), 8 warps (2m x 4n), warp tile 64x32, mma.m16n8k16.
// Grid: x = m-tiles (fast) so the 12 CTAs sharing one B-tile run concurrently.
__global__ void __launch_bounds__(256) k_gemm_bf16(const float* __restrict__ bias,
                                                   float* __restrict__ C) {
  __shared__ __align__(16) __nv_bfloat16 As[2][128][40];
  __shared__ __align__(16) __nv_bfloat16 Bs[2][128][40];
  const int m0 = blockIdx.x * 128;
  const int n0 = blockIdx.y * 128;
  const int tid = threadIdx.x;
  const int warp = tid >> 5, lane = tid & 31;
  const int g = lane >> 2, tig = lane & 3;
  const int wm = warp >> 2;   // 0..1
  const int wn = warp & 3;    // 0..3
  float acc[4][4][4] = {};
  uint4 ra[2], rb[2];

  // prefetch tile 0 (A and B both 128 rows x 32 cols = 512 uint4 each)
#pragma unroll
  for (int i = 0; i < 2; i++) {
    int lin = tid + i*256;
    int r = lin >> 2, kq = lin & 3;
    ra[i] = *(const uint4*)(g_Ap + (size_t)(m0 + r)*KEF + kq*8);
    rb[i] = *(const uint4*)(g_Bp + (size_t)(n0 + r)*KEF + kq*8);
  }
#pragma unroll
  for (int i = 0; i < 2; i++) {
    int lin = tid + i*256;
    int r = lin >> 2, kq = lin & 3;
    *(uint4*)&As[0][r][kq*8] = ra[i];
    *(uint4*)&Bs[0][r][kq*8] = rb[i];
  }
  __syncthreads();

  const int KT = KEF / 32;  // 48
  int buf = 0;
  for (int tI = 0; tI < KT; tI++) {
    if (tI+1 < KT) {
      int k0 = (tI+1)*32;
#pragma unroll
      for (int i = 0; i < 2; i++) {
        int lin = tid + i*256;
        int r = lin >> 2, kq = lin & 3;
        ra[i] = *(const uint4*)(g_Ap + (size_t)(m0 + r)*KEF + k0 + kq*8);
        rb[i] = *(const uint4*)(g_Bp + (size_t)(n0 + r)*KEF + k0 + kq*8);
      }
    }
    const uint32_t* A32 = (const uint32_t*)As[buf];
    const uint32_t* B32 = (const uint32_t*)Bs[buf];
#pragma unroll
    for (int s = 0; s < 2; s++) {
      int ko = s*8;
      uint32_t a0[4], a1[4], a2[4], a3[4];
#pragma unroll
      for (int mi = 0; mi < 4; mi++) {
        int r = wm*64 + mi*16;
        a0[mi] = A32[(r+g)*20   + ko + tig];
        a1[mi] = A32[(r+g+8)*20 + ko + tig];
        a2[mi] = A32[(r+g)*20   + ko + tig + 4];
        a3[mi] = A32[(r+g+8)*20 + ko + tig + 4];
      }
      uint32_t b0[4], b1[4];
#pragma unroll
      for (int ni = 0; ni < 4; ni++) {
        int r = wn*32 + ni*8;
        b0[ni] = B32[(r+g)*20 + ko + tig];
        b1[ni] = B32[(r+g)*20 + ko + tig + 4];
      }
#pragma unroll
      for (int mi = 0; mi < 4; mi++)
#pragma unroll
        for (int ni = 0; ni < 4; ni++)
          asm volatile("mma.sync.aligned.m16n8k16.row.col.f32.bf16.bf16.f32 "
                       "{%0,%1,%2,%3}, {%4,%5,%6,%7}, {%8,%9}, {%0,%1,%2,%3};"
                       : "+f"(acc[mi][ni][0]), "+f"(acc[mi][ni][1]),
                         "+f"(acc[mi][ni][2]), "+f"(acc[mi][ni][3])
                       : "r"(a0[mi]), "r"(a1[mi]), "r"(a2[mi]), "r"(a3[mi]),
                         "r"(b0[ni]), "r"(b1[ni]));
    }
    if (tI+1 < KT) {
      __syncthreads();
#pragma unroll
      for (int i = 0; i < 2; i++) {
        int lin = tid + i*256;
        int r = lin >> 2, kq = lin & 3;
        *(uint4*)&As[buf^1][r][kq*8] = ra[i];
        *(uint4*)&Bs[buf^1][r][kq*8] = rb[i];
      }
      __syncthreads();
      buf ^= 1;
    }
  }

  // epilogue: fp32 + bias
#pragma unroll
  for (int mi = 0; mi < 4; mi++) {
    int r = m0 + wm*64 + mi*16;
#pragma unroll
    for (int ni = 0; ni < 4; ni++) {
      int col = n0 + wn*32 + ni*8 + 2*tig;
      if (col < Vz) {
        float b0v = bias[col];
        C[(size_t)(r+g)*Vz + col]   = acc[mi][ni][0] + b0v;
        C[(size_t)(r+g+8)*Vz + col] = acc[mi][ni][2] + b0v;
      }
      if (col + 1 < Vz) {
        float b1v = bias[col+1];
        C[(size_t)(r+g)*Vz + col+1]   = acc[mi][ni][1] + b1v;
        C[(size_t)(r+g+8)*Vz + col+1] = acc[mi][ni][3] + b1v;
      }
    }
  }
}

// ============ persistent encoder ============
__global__ void __launch_bounds__(256) k_enc_run(const float* __restrict__ Whhf,
                                                 const float* __restrict__ Whhb,
                                                 const int* __restrict__ lens) {
  extern __shared__ float sm[];
  float* h_s  = sm;
  float* part = sm + 32*256;
  int ct  = blockIdx.x & 31;
  int dir = blockIdx.x >> 5;
  int j0 = ct*8;
  int tid = threadIdx.x;
  int gc = tid & 31, kg = tid >> 5;
  int g = gc >> 3, jj = gc & 7;
  const float* Whh = dir ? Whhb : Whhf;
  const float* gx  = dir ? g_gxb : g_gxf;
  float* h0 = dir ? g_hb[0] : g_hf[0];
  float* h1 = dir ? g_hb[1] : g_hf[1];

  float4 w4[8];
  {
    const float* wrow = Whh + (size_t)(g*Hz + j0 + jj)*Hz + kg*32;
#pragma unroll
    for (int q = 0; q < 8; q++) w4[q] = *(const float4*)(wrow + q*4);
  }

  int rj = tid & 7, rb = tid >> 3;
  int len_rb = lens[rb];
  float c_reg = 0.f;

  for (int t = 0; t < Sz; t++) {
    int rd = t & 1;
    const float* hrd = rd ? h1 : h0;
    float*       hwr = rd ? h0 : h1;
    int time = dir ? (Sz-1-t) : t;

#pragma unroll
    for (int i = 0; i < 8; i++) {
      int idx = tid + i*256;
      ((float4*)h_s)[idx] = ((const float4*)hrd)[idx];
    }
    __syncthreads();

    float acc[32];
#pragma unroll
    for (int b = 0; b < 32; b++) acc[b] = 0.f;
#pragma unroll
    for (int q = 0; q < 8; q++) {
      float4 w = w4[q];
      const float* hp = h_s + kg*32 + q*4;
#pragma unroll
      for (int b = 0; b < 32; b++) {
        float4 hv = *(const float4*)(hp + b*256);
        acc[b] = fmaf(w.x, hv.x, acc[b]);
        acc[b] = fmaf(w.y, hv.y, acc[b]);
        acc[b] = fmaf(w.z, hv.z, acc[b]);
        acc[b] = fmaf(w.w, hv.w, acc[b]);
      }
    }
#pragma unroll
    for (int b = 0; b < 32; b++) part[(kg*32 + gc)*37 + b] = acc[b];
    __syncthreads();

    float s0=0.f, s1=0.f, s2=0.f, s3=0.f;
#pragma unroll
    for (int kk = 0; kk < 8; kk++) {
      s0 += part[(kk*32 +      rj)*37 + rb];
      s1 += part[(kk*32 +  8 + rj)*37 + rb];
      s2 += part[(kk*32 + 16 + rj)*37 + rb];
      s3 += part[(kk*32 + 24 + rj)*37 + rb];
    }
    int jg = j0 + rj;
    const float* gxr = gx + ((size_t)(rb*Sz + time))*GEz;
    float gi = s0 + gxr[jg];
    float gf = s1 + gxr[Hz   + jg];
    float gg = s2 + gxr[2*Hz + jg];
    float go = s3 + gxr[3*Hz + jg];
    bool valid = time < len_rb;
    float hprev = h_s[rb*256 + jg];
    float cn = sigf(gf)*c_reg + sigf(gi)*tanhf(gg);
    float hn = sigf(go)*tanhf(cn);
    bool upd = (dir == 0) || valid;
    if (upd) c_reg = cn;
    hwr[rb*Hz + jg] = upd ? hn : hprev;
    g_enc[((size_t)(rb*Sz + time))*(2*Hz) + dir*Hz + jg] = valid ? hn : 0.f;

    gbar(0, t+1);
  }
}

// ============ persistent decoder (2 grid barriers per step) ============
__global__ void __launch_bounds__(256) k_dec_run(const float* __restrict__ Whhd,
                                                 const float* __restrict__ W2,
                                                 const float* __restrict__ vv,
                                                 const int* __restrict__ lens) {
  extern __shared__ float sm[];
  float* h_s  = sm;
  float* part = sm + 32*512;
  int ct = blockIdx.x;
  int j0 = ct*8;
  int tid = threadIdx.x;
  int gc = tid & 31, kg = tid >> 5;
  int g = gc >> 3, jj = gc & 7;

  float4 w4[16];
  {
    const float* wrow = Whhd + (size_t)(g*HDz + j0 + jj)*HDz + kg*64;
#pragma unroll
    for (int q = 0; q < 16; q++) w4[q] = *(const float4*)(wrow + q*4);
  }
  int qn = tid & 7, qkg = tid >> 3;
  float4 w2r[4];
  {
    const float* w2row = W2 + (size_t)(j0 + qn)*HDz + qkg*16;
#pragma unroll
    for (int q = 0; q < 4; q++) w2r[q] = *(const float4*)(w2row + q*4);
  }

  int rj = tid & 7, rb = tid >> 3;
  float c_reg = 0.f;

  for (int t = 0; t < Tz; t++) {
    int rd = t & 1;
    const float* hrd = g_hd[rd];
    float*       hwr = g_hd[rd ^ 1];

    // ---- Phase A: gates GEMM + cell ----
#pragma unroll
    for (int i = 0; i < 16; i++) {
      int idx = tid + i*256;
      ((float4*)h_s)[idx] = ((const float4*)hrd)[idx];
    }
    __syncthreads();

#pragma unroll
    for (int half = 0; half < 2; half++) {
      float acc[16];
#pragma unroll
      for (int b = 0; b < 16; b++) acc[b] = 0.f;
#pragma unroll
      for (int q = 0; q < 16; q++) {
        float4 w = w4[q];
        const float* hp = h_s + kg*64 + q*4 + half*16*512;
#pragma unroll
        for (int b = 0; b < 16; b++) {
          float4 hv = *(const float4*)(hp + b*512);
          acc[b] = fmaf(w.x, hv.x, acc[b]);
          acc[b] = fmaf(w.y, hv.y, acc[b]);
          acc[b] = fmaf(w.z, hv.z, acc[b]);
          acc[b] = fmaf(w.w, hv.w, acc[b]);
        }
      }
#pragma unroll
      for (int b = 0; b < 16; b++) part[(kg*32 + gc)*37 + half*16 + b] = acc[b];
    }
    __syncthreads();

    {
      float s0=0.f, s1=0.f, s2=0.f, s3=0.f;
#pragma unroll
      for (int kk = 0; kk < 8; kk++) {
        s0 += part[(kk*32 +      rj)*37 + rb];
        s1 += part[(kk*32 +  8 + rj)*37 + rb];
        s2 += part[(kk*32 + 16 + rj)*37 + rb];
        s3 += part[(kk*32 + 24 + rj)*37 + rb];
      }
      int jg = j0 + rj;
      const float* gxr = g_gxd + ((size_t)(rb*Tz + t))*GDz;
      float gi = s0 + gxr[jg];
      float gf = s1 + gxr[HDz   + jg];
      float gg = s2 + gxr[2*HDz + jg];
      float go = s3 + gxr[3*HDz + jg];
      float cn = sigf(gf)*c_reg + sigf(gi)*tanhf(gg);
      c_reg = cn;
      hwr[rb*HDz + jg] = sigf(go)*tanhf(cn);
    }
    gbar(1, 2*t+1);

    // ---- Phase B: qp = h_new @ W2^T ----
#pragma unroll
    for (int i = 0; i < 16; i++) {
      int idx = tid + i*256;
      ((float4*)h_s)[idx] = ((const float4*)hwr)[idx];
    }
    __syncthreads();
    {
      float acc[32];
#pragma unroll
      for (int b = 0; b < 32; b++) acc[b] = 0.f;
#pragma unroll
      for (int q = 0; q < 4; q++) {
        float4 w = w2r[q];
        const float* hp = h_s + qkg*16 + q*4;
#pragma unroll
        for (int b = 0; b < 32; b++) {
          float4 hv = *(const float4*)(hp + b*512);
          acc[b] = fmaf(w.x, hv.x, acc[b]);
          acc[b] = fmaf(w.y, hv.y, acc[b]);
          acc[b] = fmaf(w.z, hv.z, acc[b]);
          acc[b] = fmaf(w.w, hv.w, acc[b]);
        }
      }
#pragma unroll
      for (int b = 0; b < 32; b++) part[(qkg*8 + qn)*37 + b] = acc[b];
    }
    __syncthreads();
    {
      int n2 = tid & 7, b2 = tid >> 3;
      float s = 0.f;
#pragma unroll
      for (int kk = 0; kk < 32; kk++) s += part[(kk*8 + n2)*37 + b2];
      g_qp[b2*HDz + j0 + n2] = s;
    }
    gbar(1, 2*t+2);

    // ---- Phase C: attention for batch b = ct (first 32 blocks) ----
    // No trailing barrier: A(t+1) writes only g_hd[t&1], disjoint from C's reads;
    // B(t+1)'s g_qp writes are fenced by gbar(2(t+1)+1).
    if (ct < 32) {
      int b = ct;
      float* qp_s = part;
      float* e    = part + 512;
      for (int j = tid; j < HDz; j += 256) qp_s[j] = g_qp[b*HDz + j];
      __syncthreads();
      int wid = tid >> 5, lane = tid & 31;
      int len = lens[b];
      for (int s = wid; s < Sz; s += 8) {
        float p = 0.f;
        const float* kp = g_kp + ((size_t)(b*Sz + s))*HDz;
        for (int jx = lane; jx < HDz; jx += 32) p += tanhf(kp[jx] + qp_s[jx]) * vv[jx];
#pragma unroll
        for (int o = 16; o; o >>= 1) p += __shfl_xor_sync(0xffffffffu, p, o);
        if (lane == 0) e[s] = (s < len) ? p : -1e10f;
      }
      __syncthreads();
      float m = -1e30f;
#pragma unroll
      for (int s = 0; s < Sz; s++) m = fmaxf(m, e[s]);
      float ssum = 0.f;
#pragma unroll
      for (int s = 0; s < Sz; s++) ssum += expf(e[s] - m);
      __syncthreads();
      if (tid < Sz) e[tid] = expf(e[tid] - m) / ssum;
      __syncthreads();
      for (int jx = tid; jx < HDz; jx += 256) {
        float cx = 0.f;
        const float* ep = g_enc + ((size_t)b*Sz)*(2*Hz) + jx;
#pragma unroll 8
        for (int s = 0; s < Sz; s++) cx = fmaf(e[s], ep[(size_t)s*(2*Hz)], cx);
        g_hctx[((size_t)(b*Tz + t))*HDz + jx] = hwr[b*HDz + jx] + cx;
      }
      __syncthreads();   // protect smem (part) reuse by next A phase
    }
  }
}

// ---------------- loss: two-pass max + FMA-pipe poly-exp sum; grid B*T ----------------
__global__ void __launch_bounds__(256) k_loss_rows(const float* __restrict__ logits,
                                                   const int* __restrict__ oseq) {
  int row = blockIdx.x;
  const float* x = logits + (size_t)row*Vz;
  __shared__ float red[256];

  float m = -1e30f;
  for (int i = threadIdx.x; i < Vz; i += 256) m = fmaxf(m, x[i]);
  red[threadIdx.x] = m;
  __syncthreads();
  for (int o = 128; o; o >>= 1) {
    if (threadIdx.x < o) red[threadIdx.x] = fmaxf(red[threadIdx.x], red[threadIdx.x+o]);
    __syncthreads();
  }
  m = red[0];
  __syncthreads();

  float s = 0.f;
  for (int i = threadIdx.x; i < Vz; i += 256) {
    float y = (x[i] - m) * 1.4426950408889634f;
    float t = y + 12582912.0f;
    int   n = (__float_as_int(t) & 0x7FFFFF) - 0x400000;
    float f = y - (t - 12582912.0f);
    float p = 1.f + f*(0.6931471806f + f*(0.2402265069f + f*(0.0555041087f +
              f*(0.0096181291f + f*0.0013333558f))));
    n = max(n, -126);
    s += p * __int_as_float((n + 127) << 23);
  }
  red[threadIdx.x] = s;
  __syncthreads();
  for (int o = 128; o; o >>= 1) {
    if (threadIdx.x < o) red[threadIdx.x] += red[threadIdx.x+o];
    __syncthreads();
  }
  if (threadIdx.x == 0) {
    int tgt = oseq[row];
    float nll = m + logf(red[0]) - x[tgt];
    float msk = (tgt != 0) ? 1.f : 0.f;
    g_rnll[row] = nll * msk;
    g_rmsk[row] = msk;
  }
}

__global__ void k_loss_reduce(float* out, int out_size) {
  __shared__ float sa[256], sb[256];
  float a = 0.f, b = 0.f;
  for (int i = threadIdx.x; i < Bz*Tz; i += 256) { a += g_rnll[i]; b += g_rmsk[i]; }
  sa[threadIdx.x] = a; sb[threadIdx.x] = b;
  __syncthreads();
  for (int o = 128; o; o >>= 1) {
    if (threadIdx.x < o) { sa[threadIdx.x] += sa[threadIdx.x+o]; sb[threadIdx.x] += sb[threadIdx.x+o]; }
    __syncthreads();
  }
  if (threadIdx.x == 0 && out_size > Bz*Tz*Vz)
    out[Bz*Tz*Vz] = sa[0] / fmaxf(sb[0], 1.f);
}

// ---------------- host orchestration ----------------
#define ENC_SMEM ((32*256 + 8*32*37)*4)
#define DEC_SMEM ((32*512 + 8*32*37)*4)

extern "C" void kernel_launch(void* const* d_in, const int* in_sizes, int n_in,
                              void* d_out, int out_size) {
  const int*   iseq = (const int*)  d_in[0];
  const int*   lens = (const int*)  d_in[1];
  const int*   oseq = (const int*)  d_in[2];
  const float* es   = (const float*)d_in[3];
  const float* Wihf = (const float*)d_in[4];
  const float* Whhf = (const float*)d_in[5];
  const float* bf   = (const float*)d_in[6];
  const float* Wihb = (const float*)d_in[7];
  const float* Whhb = (const float*)d_in[8];
  const float* bb   = (const float*)d_in[9];
  const float* et   = (const float*)d_in[10];
  const float* Wihd = (const float*)d_in[11];
  const float* Whhd = (const float*)d_in[12];
  const float* bd   = (const float*)d_in[13];
  const float* W1   = (const float*)d_in[14];
  const float* W2   = (const float*)d_in[15];
  const float* vv   = (const float*)d_in[16];
  const float* Wo   = (const float*)d_in[17];
  const float* bo   = (const float*)d_in[18];
  float* out = (float*)d_out;

  cudaFuncSetAttribute(k_enc_run, cudaFuncAttributeMaxDynamicSharedMemorySize, ENC_SMEM);
  cudaFuncSetAttribute(k_dec_run, cudaFuncAttributeMaxDynamicSharedMemorySize, DEC_SMEM);

  void *p_x, *p_di, *p_gxf, *p_gxb, *p_gxd, *p_enc, *p_kp;
  cudaGetSymbolAddress(&p_x,    g_x);
  cudaGetSymbolAddress(&p_di,   g_di);
  cudaGetSymbolAddress(&p_gxf,  g_gxf);
  cudaGetSymbolAddress(&p_gxb,  g_gxb);
  cudaGetSymbolAddress(&p_gxd,  g_gxd);
  cudaGetSymbolAddress(&p_enc,  g_enc);
  cudaGetSymbolAddress(&p_kp,   g_kp);

  k_prep<<<1024, 256>>>(iseq, oseq, es, et);
  k_prep_w<<<4096, 256>>>(Wo);

  k_gemm128<<<dim3(GEz/128, (Bz*Sz)/128), 256>>>((const float*)p_x,  Wihf, bf,
                                                 (float*)p_gxf, Bz*Sz, GEz, Ez);
  k_gemm128<<<dim3(GEz/128, (Bz*Sz)/128), 256>>>((const float*)p_x,  Wihb, bb,
                                                 (float*)p_gxb, Bz*Sz, GEz, Ez);
  k_gemm128<<<dim3(GDz/128, (Bz*Tz)/128), 256>>>((const float*)p_di, Wihd, bd,
                                                 (float*)p_gxd, Bz*Tz, GDz, Ez);

  k_enc_run<<<64, 256, ENC_SMEM>>>(Whhf, Whhb, lens);

  k_gemm128<<<dim3(HDz/128, (Bz*Sz)/128), 256>>>((const float*)p_enc, W1, nullptr,
                                                 (float*)p_kp, Bz*Sz, HDz, HDz);

  k_dec_run<<<64, 256, DEC_SMEM>>>(Whhd, W2, vv, lens);

  k_prep_a<<<512, 256>>>();

  // logits = hctx @ Wo^T + bo via split-bf16 mma.sync (m fastest for B-tile L2 reuse)
  k_gemm_bf16<<<dim3((Bz*Tz)/128, VP2/128), 256>>>(bo, out);

  k_loss_rows<<<Bz*Tz, 256>>>(out, oseq);
  k_loss_reduce<<<1, 256>>>(out, out_size);
}

// round 17
// speedup vs baseline: 2.5772x; 1.0879x over previous
#include <cuda_runtime.h>
#include <cuda_bf16.h>
#include <cstdint>
#include <math.h>

#define Bz 32
#define Sz 64
#define Tz 48
#define Ez 128
#define Hz 256
#define HDz 512
#define Vz 32001
#define VP2 32128  /* Vz padded to /128 */
#define GEz 1024   /* 4H  */
#define GDz 2048   /* 4HD */
#define KEF 1536   /* split-bf16 effective K = 3*512 */

// ---------------- device scratch (static, allocation-free) ----------------
__device__ float g_x[Bz*Sz*Ez];
__device__ float g_di[Bz*Tz*Ez];
__device__ float g_gxf[Bz*Sz*GEz];
__device__ float g_gxb[Bz*Sz*GEz];
__device__ float g_gxd[Bz*Tz*GDz];
__device__ float g_enc[Bz*Sz*2*Hz];
__device__ float g_kp[Bz*Sz*HDz];
__device__ float g_hf[2][Bz*Hz], g_hb[2][Bz*Hz];
__device__ float g_hd[2][Bz*HDz];
__device__ float g_qp[Bz*HDz];
__device__ float g_hctx[Bz*Tz*HDz];
__device__ float g_rnll[Bz*Tz], g_rmsk[Bz*Tz];
__device__ unsigned g_rmax[Bz*Tz];                 // encoded per-row logit max
__device__ __nv_bfloat16 g_Bp[(size_t)VP2*KEF];    // [w_hi | w_hi | w_lo]
__device__ __nv_bfloat16 g_Ap[(size_t)Bz*Tz*KEF];  // [a_hi | a_lo | a_hi]

__device__ int g_bcnt[2];
__device__ volatile int g_bgen[2];

__device__ __forceinline__ float sigf(float x){ return 1.f/(1.f+expf(-x)); }

// monotonic float->uint encode (unsigned compare == float compare)
__device__ __forceinline__ unsigned fenc(float f) {
  int i = __float_as_int(f);
  return (unsigned)(i ^ ((i >> 31) | 0x80000000));
}

// grid-wide barrier for exactly 128 co-resident blocks
__device__ __forceinline__ void gbar(int id, int want) {
  __syncthreads();
  if (threadIdx.x == 0) {
    __threadfence();
    if (atomicAdd(&g_bcnt[id], 1) == 127) {
      g_bcnt[id] = 0;
      __threadfence();
      g_bgen[id] = want;
    } else {
      while (g_bgen[id] < want) __nanosleep(64);
    }
  }
  __syncthreads();
}

// ---------------- prep: embeddings, zero states, reset barriers + rowmax ----------
__global__ void k_prep(const int* __restrict__ iseq, const int* __restrict__ oseq,
                       const float* __restrict__ es, const float* __restrict__ et) {
  const int N1 = Bz*Sz*Ez;
  const int N2 = Bz*Tz*Ez;
  const int NZ = 2*Bz*Hz*2 + 2*Bz*HDz;   // 65536
  const int total = N1 + N2 + NZ + Bz*Tz;
  if (blockIdx.x == 0 && threadIdx.x == 0) {
    g_bcnt[0] = 0; g_bcnt[1] = 0; g_bgen[0] = 0; g_bgen[1] = 0;
  }
  for (int idx = blockIdx.x*blockDim.x + threadIdx.x; idx < total; idx += gridDim.x*blockDim.x) {
    int i = idx;
    if (i < N1) { int e = i % Ez; int bs = i / Ez;
      g_x[i] = es[(size_t)iseq[bs]*Ez + e]; continue; }
    i -= N1;
    if (i < N2) { int e = i % Ez; int bt = i / Ez; int t = bt % Tz; int b = bt / Tz;
      g_di[i] = (t==0) ? 0.f : et[(size_t)oseq[b*Tz + t-1]*Ez + e]; continue; }
    i -= N2;
    if (i < 16384)      ((float*)g_hf)[i] = 0.f;
    else if (i < 32768) ((float*)g_hb)[i-16384] = 0.f;
    else if (i < 65536) ((float*)g_hd)[i-32768] = 0.f;
    else                g_rmax[i-65536] = 0u;
  }
}

// ---------------- split Wo into bf16 hi/lo, K-concatenated ----------------
__global__ void k_prep_w(const float* __restrict__ Wo) {
  for (size_t idx = (size_t)blockIdx.x*blockDim.x + threadIdx.x; idx < (size_t)VP2*HDz;
       idx += (size_t)gridDim.x*blockDim.x) {
    int n = (int)(idx / HDz), k = (int)(idx - (size_t)n*HDz);
    float w = (n < Vz) ? Wo[(size_t)n*HDz + k] : 0.f;
    __nv_bfloat16 hi = __float2bfloat16(w);
    __nv_bfloat16 lo = __float2bfloat16(w - __bfloat162float(hi));
    size_t base = (size_t)n*KEF + k;
    g_Bp[base]          = hi;
    g_Bp[base + HDz]    = hi;
    g_Bp[base + 2*HDz]  = lo;
  }
}

// ---------------- split hctx into bf16 hi/lo, K-concatenated ----------------
__global__ void k_prep_a() {
  for (int idx = blockIdx.x*blockDim.x + threadIdx.x; idx < Bz*Tz*HDz; idx += gridDim.x*blockDim.x) {
    int m = idx / HDz, k = idx - (idx/HDz)*HDz;
    float v = g_hctx[idx];
    __nv_bfloat16 hi = __float2bfloat16(v);
    __nv_bfloat16 lo = __float2bfloat16(v - __bfloat162float(hi));
    size_t base = (size_t)m*KEF + k;
    g_Ap[base]          = hi;
    g_Ap[base + HDz]    = lo;
    g_Ap[base + 2*HDz]  = hi;
  }
}

// ---------------- fp32 SGEMM NT 128x128 (gx / keyproj) ----------------
__global__ void __launch_bounds__(256) k_gemm128(const float* __restrict__ A,
                                                 const float* __restrict__ Bm,
                                                 const float* __restrict__ bias,
                                                 float* __restrict__ C,
                                                 int M, int N, int K) {
  __shared__ __align__(16) float As[2][16][128];
  __shared__ __align__(16) float Bs[2][16][128];
  int n0 = blockIdx.x * 128;
  int m0 = blockIdx.y * 128;
  int tid = threadIdx.x;
  int tx = tid & 15;
  int ty = tid >> 4;
  float acc[8][8] = {};
  float4 ra[2], rb[2];

#pragma unroll
  for (int i = 0; i < 2; i++) {
    int lin = tid + i*256;
    int row = lin >> 2, c4 = lin & 3;
    ra[i] = *(const float4*)(A + (size_t)(m0 + row)*K + c4*4);
    int n = n0 + row;
    rb[i] = make_float4(0.f,0.f,0.f,0.f);
    if (n < N) rb[i] = *(const float4*)(Bm + (size_t)n*K + c4*4);
  }
#pragma unroll
  for (int i = 0; i < 2; i++) {
    int lin = tid + i*256;
    int row = lin >> 2, c4 = lin & 3;
    As[0][c4*4+0][row] = ra[i].x; As[0][c4*4+1][row] = ra[i].y;
    As[0][c4*4+2][row] = ra[i].z; As[0][c4*4+3][row] = ra[i].w;
    Bs[0][c4*4+0][row] = rb[i].x; Bs[0][c4*4+1][row] = rb[i].y;
    Bs[0][c4*4+2][row] = rb[i].z; Bs[0][c4*4+3][row] = rb[i].w;
  }
  __syncthreads();

  const int NT = K / 16;
  int buf = 0;
  for (int tI = 0; tI < NT; tI++) {
    if (tI+1 < NT) {
      int k0 = (tI+1)*16;
#pragma unroll
      for (int i = 0; i < 2; i++) {
        int lin = tid + i*256;
        int row = lin >> 2, c4 = lin & 3;
        ra[i] = *(const float4*)(A + (size_t)(m0 + row)*K + k0 + c4*4);
        int n = n0 + row;
        rb[i] = make_float4(0.f,0.f,0.f,0.f);
        if (n < N) rb[i] = *(const float4*)(Bm + (size_t)n*K + k0 + c4*4);
      }
    }
#pragma unroll
    for (int kk = 0; kk < 16; kk++) {
      float a[8], b[8];
      *(float4*)&a[0] = *(const float4*)&As[buf][kk][ty*8];
      *(float4*)&a[4] = *(const float4*)&As[buf][kk][ty*8+4];
      *(float4*)&b[0] = *(const float4*)&Bs[buf][kk][tx*8];
      *(float4*)&b[4] = *(const float4*)&Bs[buf][kk][tx*8+4];
#pragma unroll
      for (int i = 0; i < 8; i++)
#pragma unroll
        for (int j = 0; j < 8; j++) acc[i][j] = fmaf(a[i], b[j], acc[i][j]);
    }
    if (tI+1 < NT) {
#pragma unroll
      for (int i = 0; i < 2; i++) {
        int lin = tid + i*256;
        int row = lin >> 2, c4 = lin & 3;
        As[buf^1][c4*4+0][row] = ra[i].x; As[buf^1][c4*4+1][row] = ra[i].y;
        As[buf^1][c4*4+2][row] = ra[i].z; As[buf^1][c4*4+3][row] = ra[i].w;
        Bs[buf^1][c4*4+0][row] = rb[i].x; Bs[buf^1][c4*4+1][row] = rb[i].y;
        Bs[buf^1][c4*4+2][row] = rb[i].z; Bs[buf^1][c4*4+3][row] = rb[i].w;
      }
      __syncthreads();
      buf ^= 1;
    }
  }
#pragma unroll
  for (int i = 0; i < 8; i++) {
    int mrow = m0 + ty*8 + i;
#pragma unroll
    for (int j = 0; j < 8; j++) {
      int n = n0 + tx*8 + j;
      if (n < N) C[(size_t)mrow*N + n] = acc[i][j] + (bias ? bias[n] : 0.f);
    }
  }
}

// ---------------- split-bf16 mma.sync GEMM + fused row-max ----------------
// A': [1536][KEF] bf16, B': [VP2][KEF] bf16, C: [1536][Vz] fp32.
// block 128(M) x 128(N), 8 warps (2m x 4n), warp tile 64x32, mma.m16n8k16.
// Grid: x = m-tiles (fast) so the 12 CTAs sharing one B-tile run concurrently.
__global__ void __launch_bounds__(256) k_gemm_bf16(const float* __restrict__ bias,
                                                   float* __restrict__ C) {
  __shared__ __align__(16) __nv_bfloat16 As[2][128][40];
  __shared__ __align__(16) __nv_bfloat16 Bs[2][128][40];
  __shared__ unsigned s_rmax[128];
  const int m0 = blockIdx.x * 128;
  const int n0 = blockIdx.y * 128;
  const int tid = threadIdx.x;
  const int warp = tid >> 5, lane = tid & 31;
  const int g = lane >> 2, tig = lane & 3;
  const int wm = warp >> 2;   // 0..1
  const int wn = warp & 3;    // 0..3
  float acc[4][4][4] = {};
  uint4 ra[2], rb[2];

  if (tid < 128) s_rmax[tid] = 0u;

#pragma unroll
  for (int i = 0; i < 2; i++) {
    int lin = tid + i*256;
    int r = lin >> 2, kq = lin & 3;
    ra[i] = *(const uint4*)(g_Ap + (size_t)(m0 + r)*KEF + kq*8);
    rb[i] = *(const uint4*)(g_Bp + (size_t)(n0 + r)*KEF + kq*8);
  }
#pragma unroll
  for (int i = 0; i < 2; i++) {
    int lin = tid + i*256;
    int r = lin >> 2, kq = lin & 3;
    *(uint4*)&As[0][r][kq*8] = ra[i];
    *(uint4*)&Bs[0][r][kq*8] = rb[i];
  }
  __syncthreads();

  const int KT = KEF / 32;  // 48
  int buf = 0;
  for (int tI = 0; tI < KT; tI++) {
    if (tI+1 < KT) {
      int k0 = (tI+1)*32;
#pragma unroll
      for (int i = 0; i < 2; i++) {
        int lin = tid + i*256;
        int r = lin >> 2, kq = lin & 3;
        ra[i] = *(const uint4*)(g_Ap + (size_t)(m0 + r)*KEF + k0 + kq*8);
        rb[i] = *(const uint4*)(g_Bp + (size_t)(n0 + r)*KEF + k0 + kq*8);
      }
    }
    const uint32_t* A32 = (const uint32_t*)As[buf];
    const uint32_t* B32 = (const uint32_t*)Bs[buf];
#pragma unroll
    for (int s = 0; s < 2; s++) {
      int ko = s*8;
      uint32_t a0[4], a1[4], a2[4], a3[4];
#pragma unroll
      for (int mi = 0; mi < 4; mi++) {
        int r = wm*64 + mi*16;
        a0[mi] = A32[(r+g)*20   + ko + tig];
        a1[mi] = A32[(r+g+8)*20 + ko + tig];
        a2[mi] = A32[(r+g)*20   + ko + tig + 4];
        a3[mi] = A32[(r+g+8)*20 + ko + tig + 4];
      }
      uint32_t b0[4], b1[4];
#pragma unroll
      for (int ni = 0; ni < 4; ni++) {
        int r = wn*32 + ni*8;
        b0[ni] = B32[(r+g)*20 + ko + tig];
        b1[ni] = B32[(r+g)*20 + ko + tig + 4];
      }
#pragma unroll
      for (int mi = 0; mi < 4; mi++)
#pragma unroll
        for (int ni = 0; ni < 4; ni++)
          asm volatile("mma.sync.aligned.m16n8k16.row.col.f32.bf16.bf16.f32 "
                       "{%0,%1,%2,%3}, {%4,%5,%6,%7}, {%8,%9}, {%0,%1,%2,%3};"
                       : "+f"(acc[mi][ni][0]), "+f"(acc[mi][ni][1]),
                         "+f"(acc[mi][ni][2]), "+f"(acc[mi][ni][3])
                       : "r"(a0[mi]), "r"(a1[mi]), "r"(a2[mi]), "r"(a3[mi]),
                         "r"(b0[ni]), "r"(b1[ni]));
    }
    if (tI+1 < KT) {
      __syncthreads();
#pragma unroll
      for (int i = 0; i < 2; i++) {
        int lin = tid + i*256;
        int r = lin >> 2, kq = lin & 3;
        *(uint4*)&As[buf^1][r][kq*8] = ra[i];
        *(uint4*)&Bs[buf^1][r][kq*8] = rb[i];
      }
      __syncthreads();
      buf ^= 1;
    }
  }

  // epilogue: fp32 + bias, tracking per-row max of stored values
#pragma unroll
  for (int mi = 0; mi < 4; mi++) {
    int rl = wm*64 + mi*16 + g;       // local row (0..127)
    int r = m0 + rl;
    float mx0 = -3.4e38f, mx1 = -3.4e38f;
#pragma unroll
    for (int ni = 0; ni < 4; ni++) {
      int col = n0 + wn*32 + ni*8 + 2*tig;
      if (col < Vz) {
        float b0v = bias[col];
        float v0 = acc[mi][ni][0] + b0v;
        float v2 = acc[mi][ni][2] + b0v;
        C[(size_t)r*Vz + col]     = v0;
        C[(size_t)(r+8)*Vz + col] = v2;
        mx0 = fmaxf(mx0, v0); mx1 = fmaxf(mx1, v2);
      }
      if (col + 1 < Vz) {
        float b1v = bias[col+1];
        float v1 = acc[mi][ni][1] + b1v;
        float v3 = acc[mi][ni][3] + b1v;
        C[(size_t)r*Vz + col+1]     = v1;
        C[(size_t)(r+8)*Vz + col+1] = v3;
        mx0 = fmaxf(mx0, v1); mx1 = fmaxf(mx1, v3);
      }
    }
    atomicMax(&s_rmax[rl],     fenc(mx0));
    atomicMax(&s_rmax[rl + 8], fenc(mx1));
  }
  __syncthreads();
  if (tid < 128) atomicMax(&g_rmax[m0 + tid], s_rmax[tid]);
}

// ============ persistent encoder: 128 blocks = dir(2) x ct(64; 4 j each) ============
__global__ void __launch_bounds__(256) k_enc_run(const float* __restrict__ Whhf,
                                                 const float* __restrict__ Whhb,
                                                 const int* __restrict__ lens) {
  extern __shared__ float sm[];
  float* h_s  = sm;               // 32*256
  float* part = sm + 32*256;      // 256*37
  int ct  = blockIdx.x & 63;
  int dir = blockIdx.x >> 6;
  int j0 = ct*4;
  int tid = threadIdx.x;
  int gc = tid & 15, kg = tid >> 4;       // 16 gc x 16 kg(16 k each)
  int g = gc >> 2, jj = gc & 3;
  const float* Whh = dir ? Whhb : Whhf;
  const float* gx  = dir ? g_gxb : g_gxf;
  float* h0 = dir ? g_hb[0] : g_hf[0];
  float* h1 = dir ? g_hb[1] : g_hf[1];

  float4 w4[4];
  {
    const float* wrow = Whh + (size_t)(g*Hz + j0 + jj)*Hz + kg*16;
#pragma unroll
    for (int q = 0; q < 4; q++) w4[q] = *(const float4*)(wrow + q*4);
  }

  int rj = tid & 3, rb = tid >> 2;        // reduce role (tid<128)
  int len_rb = (tid < 128) ? lens[rb] : 0;
  float c_reg = 0.f;

  for (int t = 0; t < Sz; t++) {
    int rd = t & 1;
    const float* hrd = rd ? h1 : h0;
    float*       hwr = rd ? h0 : h1;
    int time = dir ? (Sz-1-t) : t;

#pragma unroll
    for (int i = 0; i < 8; i++) {
      int idx = tid + i*256;
      ((float4*)h_s)[idx] = ((const float4*)hrd)[idx];
    }
    __syncthreads();

    float acc[32];
#pragma unroll
    for (int b = 0; b < 32; b++) acc[b] = 0.f;
#pragma unroll
    for (int q = 0; q < 4; q++) {
      float4 w = w4[q];
      const float* hp = h_s + kg*16 + q*4;
#pragma unroll
      for (int b = 0; b < 32; b++) {
        float4 hv = *(const float4*)(hp + b*256);
        acc[b] = fmaf(w.x, hv.x, acc[b]);
        acc[b] = fmaf(w.y, hv.y, acc[b]);
        acc[b] = fmaf(w.z, hv.z, acc[b]);
        acc[b] = fmaf(w.w, hv.w, acc[b]);
      }
    }
#pragma unroll
    for (int b = 0; b < 32; b++) part[(kg*16 + gc)*37 + b] = acc[b];
    __syncthreads();

    if (tid < 128) {
      float s0=0.f, s1=0.f, s2=0.f, s3=0.f;
#pragma unroll
      for (int kk = 0; kk < 16; kk++) {
        s0 += part[(kk*16 +      rj)*37 + rb];
        s1 += part[(kk*16 +  4 + rj)*37 + rb];
        s2 += part[(kk*16 +  8 + rj)*37 + rb];
        s3 += part[(kk*16 + 12 + rj)*37 + rb];
      }
      int jg = j0 + rj;
      const float* gxr = gx + ((size_t)(rb*Sz + time))*GEz;
      float gi = s0 + gxr[jg];
      float gf = s1 + gxr[Hz   + jg];
      float gg = s2 + gxr[2*Hz + jg];
      float go = s3 + gxr[3*Hz + jg];
      bool valid = time < len_rb;
      float hprev = h_s[rb*256 + jg];
      float cn = sigf(gf)*c_reg + sigf(gi)*tanhf(gg);
      float hn = sigf(go)*tanhf(cn);
      bool upd = (dir == 0) || valid;
      if (upd) c_reg = cn;
      hwr[rb*Hz + jg] = upd ? hn : hprev;
      g_enc[((size_t)(rb*Sz + time))*(2*Hz) + dir*Hz + jg] = valid ? hn : 0.f;
    }
    gbar(0, t+1);
  }
}

// ============ persistent decoder: 128 blocks (4 j each of 512) ============
__global__ void __launch_bounds__(256) k_dec_run(const float* __restrict__ Whhd,
                                                 const float* __restrict__ W2,
                                                 const float* __restrict__ vv,
                                                 const int* __restrict__ lens) {
  extern __shared__ float sm[];
  float* h_s  = sm;               // 32*512
  float* part = sm + 32*512;      // 256*37
  int ct = blockIdx.x;
  int j0 = ct*4;
  int tid = threadIdx.x;
  int gc = tid & 15, kg = tid >> 4;       // 16 gc x 16 kg(32 k each)
  int g = gc >> 2, jj = gc & 3;

  float4 w4[8];
  {
    const float* wrow = Whhd + (size_t)(g*HDz + j0 + jj)*HDz + kg*32;
#pragma unroll
    for (int q = 0; q < 8; q++) w4[q] = *(const float4*)(wrow + q*4);
  }
  int qn = tid & 3, qkg = tid >> 2;       // qp: 4 n x 64 kg(8 k each)
  float4 w2r[2];
  {
    const float* w2row = W2 + (size_t)(j0 + qn)*HDz + qkg*8;
#pragma unroll
    for (int q = 0; q < 2; q++) w2r[q] = *(const float4*)(w2row + q*4);
  }

  int rj = tid & 3, rb = tid >> 2;        // reduce role (tid<128)
  float c_reg = 0.f;

  for (int t = 0; t < Tz; t++) {
    int rd = t & 1;
    const float* hrd = g_hd[rd];
    float*       hwr = g_hd[rd ^ 1];

    // ---- Phase A: gates GEMM + cell ----
#pragma unroll
    for (int i = 0; i < 16; i++) {
      int idx = tid + i*256;
      ((float4*)h_s)[idx] = ((const float4*)hrd)[idx];
    }
    __syncthreads();

#pragma unroll
    for (int half = 0; half < 2; half++) {
      float acc[16];
#pragma unroll
      for (int b = 0; b < 16; b++) acc[b] = 0.f;
#pragma unroll
      for (int q = 0; q < 8; q++) {
        float4 w = w4[q];
        const float* hp = h_s + kg*32 + q*4 + half*16*512;
#pragma unroll
        for (int b = 0; b < 16; b++) {
          float4 hv = *(const float4*)(hp + b*512);
          acc[b] = fmaf(w.x, hv.x, acc[b]);
          acc[b] = fmaf(w.y, hv.y, acc[b]);
          acc[b] = fmaf(w.z, hv.z, acc[b]);
          acc[b] = fmaf(w.w, hv.w, acc[b]);
        }
      }
#pragma unroll
      for (int b = 0; b < 16; b++) part[(kg*16 + gc)*37 + half*16 + b] = acc[b];
    }
    __syncthreads();

    if (tid < 128) {
      float s0=0.f, s1=0.f, s2=0.f, s3=0.f;
#pragma unroll
      for (int kk = 0; kk < 16; kk++) {
        s0 += part[(kk*16 +      rj)*37 + rb];
        s1 += part[(kk*16 +  4 + rj)*37 + rb];
        s2 += part[(kk*16 +  8 + rj)*37 + rb];
        s3 += part[(kk*16 + 12 + rj)*37 + rb];
      }
      int jg = j0 + rj;
      const float* gxr = g_gxd + ((size_t)(rb*Tz + t))*GDz;
      float gi = s0 + gxr[jg];
      float gf = s1 + gxr[HDz   + jg];
      float gg = s2 + gxr[2*HDz + jg];
      float go = s3 + gxr[3*HDz + jg];
      float cn = sigf(gf)*c_reg + sigf(gi)*tanhf(gg);
      c_reg = cn;
      hwr[rb*HDz + jg] = sigf(go)*tanhf(cn);
    }
    gbar(1, 2*t+1);

    // ---- Phase B: qp = h_new @ W2^T ----
#pragma unroll
    for (int i = 0; i < 16; i++) {
      int idx = tid + i*256;
      ((float4*)h_s)[idx] = ((const float4*)hwr)[idx];
    }
    __syncthreads();
    {
      float acc[32];
#pragma unroll
      for (int b = 0; b < 32; b++) acc[b] = 0.f;
#pragma unroll
      for (int q = 0; q < 2; q++) {
        float4 w = w2r[q];
        const float* hp = h_s + qkg*8 + q*4;
#pragma unroll
        for (int b = 0; b < 32; b++) {
          float4 hv = *(const float4*)(hp + b*512);
          acc[b] = fmaf(w.x, hv.x, acc[b]);
          acc[b] = fmaf(w.y, hv.y, acc[b]);
          acc[b] = fmaf(w.z, hv.z, acc[b]);
          acc[b] = fmaf(w.w, hv.w, acc[b]);
        }
      }
#pragma unroll
      for (int b = 0; b < 32; b++) part[(qkg*4 + qn)*37 + b] = acc[b];
    }
    __syncthreads();
    if (tid < 128) {
      int n2 = tid & 3, b2 = tid >> 2;
      float s = 0.f;
#pragma unroll
      for (int kk = 0; kk < 64; kk++) s += part[(kk*4 + n2)*37 + b2];
      g_qp[b2*HDz + j0 + n2] = s;
    }
    gbar(1, 2*t+2);

    // ---- Phase C: attention for batch b = ct (first 32 blocks) ----
    if (ct < 32) {
      int b = ct;
      float* qp_s = part;
      float* e    = part + 512;
      for (int j = tid; j < HDz; j += 256) qp_s[j] = g_qp[b*HDz + j];
      __syncthreads();
      int wid = tid >> 5, lane = tid & 31;
      int len = lens[b];
      for (int s = wid; s < Sz; s += 8) {
        float p = 0.f;
        const float* kp = g_kp + ((size_t)(b*Sz + s))*HDz;
        for (int jx = lane; jx < HDz; jx += 32) p += tanhf(kp[jx] + qp_s[jx]) * vv[jx];
#pragma unroll
        for (int o = 16; o; o >>= 1) p += __shfl_xor_sync(0xffffffffu, p, o);
        if (lane == 0) e[s] = (s < len) ? p : -1e10f;
      }
      __syncthreads();
      float m = -1e30f;
#pragma unroll
      for (int s = 0; s < Sz; s++) m = fmaxf(m, e[s]);
      float ssum = 0.f;
#pragma unroll
      for (int s = 0; s < Sz; s++) ssum += expf(e[s] - m);
      __syncthreads();
      if (tid < Sz) e[tid] = expf(e[tid] - m) / ssum;
      __syncthreads();
      for (int jx = tid; jx < HDz; jx += 256) {
        float cx = 0.f;
        const float* ep = g_enc + ((size_t)b*Sz)*(2*Hz) + jx;
#pragma unroll 8
        for (int s = 0; s < Sz; s++) cx = fmaf(e[s], ep[(size_t)s*(2*Hz)], cx);
        g_hctx[((size_t)(b*Tz + t))*HDz + jx] = hwr[b*HDz + jx] + cx;
      }
      __syncthreads();   // protect smem (part) reuse by next A phase
    }
  }
}

// ---------------- loss: single pass using fused row max; grid B*T ----------------
__global__ void __launch_bounds__(256) k_loss_rows(const float* __restrict__ logits,
                                                   const int* __restrict__ oseq) {
  int row = blockIdx.x;
  const float* x = logits + (size_t)row*Vz;
  __shared__ float red[256];

  unsigned u = g_rmax[row];
  int iv = ((int)u < 0) ? (int)(u ^ 0x80000000u) : ~(int)u;
  float m = __int_as_float(iv);

  float s = 0.f;
  for (int i = threadIdx.x; i < Vz; i += 256) {
    float y = (x[i] - m) * 1.4426950408889634f;
    float t = y + 12582912.0f;
    int   n = (__float_as_int(t) & 0x7FFFFF) - 0x400000;
    float f = y - (t - 12582912.0f);
    float p = 1.f + f*(0.6931471806f + f*(0.2402265069f + f*(0.0555041087f +
              f*(0.0096181291f + f*0.0013333558f))));
    n = max(n, -126);
    s += p * __int_as_float((n + 127) << 23);
  }
  red[threadIdx.x] = s;
  __syncthreads();
  for (int o = 128; o; o >>= 1) {
    if (threadIdx.x < o) red[threadIdx.x] += red[threadIdx.x+o];
    __syncthreads();
  }
  if (threadIdx.x == 0) {
    int tgt = oseq[row];
    float nll = m + logf(red[0]) - x[tgt];
    float msk = (tgt != 0) ? 1.f : 0.f;
    g_rnll[row] = nll * msk;
    g_rmsk[row] = msk;
  }
}

__global__ void k_loss_reduce(float* out, int out_size) {
  __shared__ float sa[256], sb[256];
  float a = 0.f, b = 0.f;
  for (int i = threadIdx.x; i < Bz*Tz; i += 256) { a += g_rnll[i]; b += g_rmsk[i]; }
  sa[threadIdx.x] = a; sb[threadIdx.x] = b;
  __syncthreads();
  for (int o = 128; o; o >>= 1) {
    if (threadIdx.x < o) { sa[threadIdx.x] += sa[threadIdx.x+o]; sb[threadIdx.x] += sb[threadIdx.x+o]; }
    __syncthreads();
  }
  if (threadIdx.x == 0 && out_size > Bz*Tz*Vz)
    out[Bz*Tz*Vz] = sa[0] / fmaxf(sb[0], 1.f);
}

// ---------------- host orchestration ----------------
#define ENC_SMEM ((32*256 + 256*37)*4)
#define DEC_SMEM ((32*512 + 256*37)*4)

extern "C" void kernel_launch(void* const* d_in, const int* in_sizes, int n_in,
                              void* d_out, int out_size) {
  const int*   iseq = (const int*)  d_in[0];
  const int*   lens = (const int*)  d_in[1];
  const int*   oseq = (const int*)  d_in[2];
  const float* es   = (const float*)d_in[3];
  const float* Wihf = (const float*)d_in[4];
  const float* Whhf = (const float*)d_in[5];
  const float* bf   = (const float*)d_in[6];
  const float* Wihb = (const float*)d_in[7];
  const float* Whhb = (const float*)d_in[8];
  const float* bb   = (const float*)d_in[9];
  const float* et   = (const float*)d_in[10];
  const float* Wihd = (const float*)d_in[11];
  const float* Whhd = (const float*)d_in[12];
  const float* bd   = (const float*)d_in[13];
  const float* W1   = (const float*)d_in[14];
  const float* W2   = (const float*)d_in[15];
  const float* vv   = (const float*)d_in[16];
  const float* Wo   = (const float*)d_in[17];
  const float* bo   = (const float*)d_in[18];
  float* out = (float*)d_out;

  cudaFuncSetAttribute(k_enc_run, cudaFuncAttributeMaxDynamicSharedMemorySize, ENC_SMEM);
  cudaFuncSetAttribute(k_dec_run, cudaFuncAttributeMaxDynamicSharedMemorySize, DEC_SMEM);

  void *p_x, *p_di, *p_gxf, *p_gxb, *p_gxd, *p_enc, *p_kp;
  cudaGetSymbolAddress(&p_x,    g_x);
  cudaGetSymbolAddress(&p_di,   g_di);
  cudaGetSymbolAddress(&p_gxf,  g_gxf);
  cudaGetSymbolAddress(&p_gxb,  g_gxb);
  cudaGetSymbolAddress(&p_gxd,  g_gxd);
  cudaGetSymbolAddress(&p_enc,  g_enc);
  cudaGetSymbolAddress(&p_kp,   g_kp);

  k_prep<<<1024, 256>>>(iseq, oseq, es, et);
  k_prep_w<<<4096, 256>>>(Wo);

  k_gemm128<<<dim3(GEz/128, (Bz*Sz)/128), 256>>>((const float*)p_x,  Wihf, bf,
                                                 (float*)p_gxf, Bz*Sz, GEz, Ez);
  k_gemm128<<<dim3(GEz/128, (Bz*Sz)/128), 256>>>((const float*)p_x,  Wihb, bb,
                                                 (float*)p_gxb, Bz*Sz, GEz, Ez);
  k_gemm128<<<dim3(GDz/128, (Bz*Tz)/128), 256>>>((const float*)p_di, Wihd, bd,
                                                 (float*)p_gxd, Bz*Tz, GDz, Ez);

  k_enc_run<<<128, 256, ENC_SMEM>>>(Whhf, Whhb, lens);

  k_gemm128<<<dim3(HDz/128, (Bz*Sz)/128), 256>>>((const float*)p_enc, W1, nullptr,
                                                 (float*)p_kp, Bz*Sz, HDz, HDz);

  k_dec_run<<<128, 256, DEC_SMEM>>>(Whhd, W2, vv, lens);

  k_prep_a<<<512, 256>>>();

  // logits = hctx @ Wo^T + bo via split-bf16 mma.sync (m fastest for B-tile L2 reuse)
  k_gemm_bf16<<<dim3((Bz*Tz)/128, VP2/128), 256>>>(bo, out);

  k_loss_rows<<<Bz*Tz, 256>>>(out, oseq);
  k_loss_reduce<<<1, 256>>>(out, out_size);
}